// round 13
// baseline (speedup 1.0000x reference)
#include <cuda_runtime.h>
#include <cuda_bf16.h>
#include <cuda_fp16.h>
#include <math.h>
#include <stdint.h>

// ---------------------------------------------------------------------------
// n=4, C=128, H=W=64, K_SIZE=5 (K2=25), N_HEAD=4, d=32
// Inputs: q, k, v, flow, Wq, Wk, Wv, Wfc
// Output: concat( out[4,128,64,64], attn[4,4,25,64,64] )
// ---------------------------------------------------------------------------

#define NB      4
#define CC      128
#define WW      64
#define HW      4096
#define NPIX    (NB*HW)
#define PLANE   (CC*HW)
#define K2      25
#define NHEAD   4

#define PW2     20                  // W packed-bf16 row stride (u32)

// qkv GEMM smem (u32), double buffered: X planes pre-split
#define QX       136                // X plane row stride (banks 8*qlan+qid)
#define Q_XL_OFF 2176               // 16*136
#define Q_WH_OFF 4352
#define Q_WL_OFF 6912               // 4352 + 128*20
#define Q_STAGE  9472               // 37888 B/stage

// out GEMM smem (u32), double buffered
#define O_XL_OFF 1280               // 64 x 20 per plane
#define O_WH_OFF 2560
#define O_WL_OFF 5120
#define O_STAGE  7680               // 30720 B/stage

#define WSZ     8192                // per-weight pre-split plane (128 o x 64 k2)

__device__ float    g_qp[NB*HW*CC];   // NHWC fp32, pre-scaled by 1/sqrt(d)
__device__ float    g_kp[NB*HW*CC];   // NHWC fp32
__device__ __half   g_vph[NB*HW*CC];  // NHWC fp16
__device__ uint32_t g_opH[NB*HW*64];  // attn output, packed bf16 hi pairs
__device__ uint32_t g_opL[NB*HW*64];  // attn output, packed bf16 lo pairs
__device__ uint32_t g_wH[4*WSZ];
__device__ uint32_t g_wL[4*WSZ];
__device__ uint32_t g_xH[3*NB*64*HW]; // q/k/v pre-split hi planes [t][n][k2][pix]
__device__ uint32_t g_xL[3*NB*64*HW]; // lo planes

// ---------------------------------------------------------------------------
// bf16x3 helpers
// ---------------------------------------------------------------------------
__device__ __forceinline__ uint16_t bfb(float f) {
    __nv_bfloat16 h = __float2bfloat16_rn(f);
    return *reinterpret_cast<uint16_t*>(&h);
}
__device__ __forceinline__ void sp2(float f0, float f1, uint32_t& ph, uint32_t& pl) {
    uint16_t h0 = bfb(f0), h1 = bfb(f1);
    float r0 = f0 - __uint_as_float((uint32_t)h0 << 16);   // exact
    float r1 = f1 - __uint_as_float((uint32_t)h1 << 16);
    uint16_t l0 = bfb(r0), l1 = bfb(r1);
    ph = ((uint32_t)h1 << 16) | h0;
    pl = ((uint32_t)l1 << 16) | l0;
}
__device__ __forceinline__ void mma_bf16(float* c, const uint32_t* a,
                                         uint32_t b0, uint32_t b1) {
    asm volatile(
        "mma.sync.aligned.m16n8k16.row.col.f32.bf16.bf16.f32 "
        "{%0,%1,%2,%3}, {%4,%5,%6,%7}, {%8,%9}, {%0,%1,%2,%3};\n"
        : "+f"(c[0]), "+f"(c[1]), "+f"(c[2]), "+f"(c[3])
        : "r"(a[0]), "r"(a[1]), "r"(a[2]), "r"(a[3]), "r"(b0), "r"(b1));
}
__device__ __forceinline__ void cp_async16(uint32_t dst_smem, const void* src) {
    asm volatile("cp.async.cg.shared.global [%0], [%1], 16;\n"
                 :: "r"(dst_smem), "l"(src));
}

// ---------------------------------------------------------------------------
// packed f32x2 helpers (attn kernel)
// ---------------------------------------------------------------------------
typedef unsigned long long u64;
__device__ __forceinline__ u64 pk2(float x, float y) {
    u64 r; asm("mov.b64 %0, {%1, %2};" : "=l"(r) : "f"(x), "f"(y)); return r;
}
__device__ __forceinline__ void up2(u64 v, float& x, float& y) {
    asm("mov.b64 {%0, %1}, %2;" : "=f"(x), "=f"(y) : "l"(v));
}
__device__ __forceinline__ u64 fma2(u64 a, u64 b, u64 c) {
    u64 d; asm("fma.rn.f32x2 %0, %1, %2, %3;" : "=l"(d) : "l"(a), "l"(b), "l"(c));
    return d;
}

// ---------------------------------------------------------------------------
// Pre-split all 4 weight matrices into packed bf16 hi/lo planes.
// ---------------------------------------------------------------------------
__global__ __launch_bounds__(256)
void presplit_w(const float* __restrict__ Wq, const float* __restrict__ Wk,
                const float* __restrict__ Wv, const float* __restrict__ Wfc)
{
    const int w = blockIdx.y;
    const float* W = (w == 0) ? Wq : (w == 1) ? Wk : (w == 2) ? Wv : Wfc;
    uint32_t* H = g_wH + w * WSZ;
    uint32_t* L = g_wL + w * WSZ;
    int base = blockIdx.x * 2048 + threadIdx.x;
    #pragma unroll
    for (int it = 0; it < 8; it++) {
        int idx = base + it * 256;
        float2 wv = *(const float2*)&W[idx * 2];
        uint32_t ph, pl; sp2(wv.x, wv.y, ph, pl);
        H[idx] = ph;
        L[idx] = pl;
    }
}

// ---------------------------------------------------------------------------
// Pre-split q/k/v (NCHW f32) into packed bf16 k-pair planes [t][n][k2][pix].
// block = (k2, n, t); reads two channel rows, packs (2k2, 2k2+1) per pixel.
// ---------------------------------------------------------------------------
__global__ __launch_bounds__(256)
void presplit_x(const float* __restrict__ q, const float* __restrict__ k,
                const float* __restrict__ v)
{
    const int k2 = blockIdx.x;      // 0..63
    const int n  = blockIdx.y;      // 0..3
    const int t  = blockIdx.z;      // 0..2
    const float* X = (t == 0) ? q : (t == 1) ? k : v;
    const float* r0 = X + ((size_t)n * CC + 2 * k2) * HW;
    const float* r1 = r0 + HW;
    uint32_t* H = g_xH + (((size_t)t * NB + n) * 64 + k2) * HW;
    uint32_t* L = g_xL + (((size_t)t * NB + n) * 64 + k2) * HW;
    #pragma unroll
    for (int it = 0; it < 16; it++) {
        int p = threadIdx.x + it * 256;
        uint32_t ph, pl;
        sp2(r0[p], r1[p], ph, pl);
        H[p] = ph;
        L[p] = pl;
    }
}

// ---------------------------------------------------------------------------
// qkv bf16x3 GEMM: X pre-split planes (no cvt in mainloop). BM=128.
// YMODE 1: f32 NHWC out.  YMODE 2: fp16 NHWC out.
// ---------------------------------------------------------------------------
template<int YMODE>
__device__ __forceinline__
void qkv_core(const uint32_t* __restrict__ WH, const uint32_t* __restrict__ WL,
              const uint32_t* __restrict__ XH, const uint32_t* __restrict__ XL,
              void* __restrict__ Y, float scale)
{
    extern __shared__ uint32_t sm[];

    const int tid   = threadIdx.x;
    const int warp  = tid >> 5;
    const int lane  = tid & 31;
    const int qid   = lane >> 2;
    const int qlan  = lane & 3;
    const int pm    = (warp & 3) * 32;
    const int on    = (warp >> 2) * 64;
    const int n     = blockIdx.y;
    const int pix0  = blockIdx.x * 128;

    const uint32_t smb = (uint32_t)__cvta_generic_to_shared(sm);

    float acc[2][8][4];
    #pragma unroll
    for (int am = 0; am < 2; am++)
        #pragma unroll
        for (int bn = 0; bn < 8; bn++)
            #pragma unroll
            for (int j = 0; j < 4; j++) acc[am][bn][j] = 0.f;

    auto load_stage = [&](int kt, int s) {
        const uint32_t sb = smb + (uint32_t)(s * Q_STAGE) * 4;
        // X planes: 2 x 16 rows x 128 u32 = 1024 chunks
        #pragma unroll
        for (int it = 0; it < 4; it++) {
            int idx = tid + it * 256;
            int plane = idx >> 9;
            int row = (idx >> 5) & 15;
            int c = idx & 31;
            const uint32_t* srcb = plane ? XL : XH;
            const uint32_t* src = srcb + (size_t)(kt * 16 + row) * HW + pix0 + c * 4;
            uint32_t dst = sb + (uint32_t)((plane ? Q_XL_OFF : 0)
                                           + row * QX + c * 4) * 4;
            cp_async16(dst, src);
        }
        // W planes: 2 x 128 rows x 4 chunks
        #pragma unroll
        for (int it = 0; it < 4; it++) {
            int idx = tid + it * 256;
            int half = idx >> 9;
            int r = (idx >> 2) & 127;
            int c = idx & 3;
            const uint32_t* src = (half ? WL : WH) + r * 64 + kt * 16 + c * 4;
            uint32_t dst = sb + (uint32_t)((half ? Q_WL_OFF : Q_WH_OFF)
                                           + r * PW2 + c * 4) * 4;
            cp_async16(dst, src);
        }
    };

    load_stage(0, 0);
    asm volatile("cp.async.commit_group;\n");

    #pragma unroll
    for (int it = 0; it < 4; it++) {
        if (it < 3) {
            load_stage(it + 1, (it + 1) & 1);
            asm volatile("cp.async.commit_group;\n");
            asm volatile("cp.async.wait_group 1;\n");
        } else {
            asm volatile("cp.async.wait_group 0;\n");
        }
        __syncthreads();

        const int s = it & 1;
        const uint32_t* XsH = sm + s * Q_STAGE;
        const uint32_t* XsL = sm + s * Q_STAGE + Q_XL_OFF;
        const uint32_t* WsH = sm + s * Q_STAGE + Q_WH_OFF;
        const uint32_t* WsL = sm + s * Q_STAGE + Q_WL_OFF;

        #pragma unroll
        for (int ks = 0; ks < 2; ks++) {
            const int k2c = ks * 8 + qlan;

            uint32_t aH[2][4], aL[2][4];
            #pragma unroll
            for (int am = 0; am < 2; am++) {
                const int r = pm + am * 16 + qid;
                aH[am][0] = XsH[k2c * QX + r];
                aH[am][1] = XsH[k2c * QX + r + 8];
                aH[am][2] = XsH[(k2c + 4) * QX + r];
                aH[am][3] = XsH[(k2c + 4) * QX + r + 8];
                aL[am][0] = XsL[k2c * QX + r];
                aL[am][1] = XsL[k2c * QX + r + 8];
                aL[am][2] = XsL[(k2c + 4) * QX + r];
                aL[am][3] = XsL[(k2c + 4) * QX + r + 8];
            }
            #pragma unroll
            for (int bn = 0; bn < 8; bn++) {
                int bo = (on + bn * 8 + qid) * PW2 + ks * 8 + qlan;
                uint32_t bH0 = WsH[bo], bH1 = WsH[bo + 4];
                uint32_t bL0 = WsL[bo], bL1 = WsL[bo + 4];
                #pragma unroll
                for (int am = 0; am < 2; am++) {
                    mma_bf16(acc[am][bn], aH[am], bH0, bH1);
                    mma_bf16(acc[am][bn], aH[am], bL0, bL1);
                    mma_bf16(acc[am][bn], aL[am], bH0, bH1);
                }
            }
        }
        if (it < 3) __syncthreads();
    }

    // ---- epilogue ----
    if (YMODE == 1) {
        float* Yn = (float*)Y + (size_t)n * PLANE;
        #pragma unroll
        for (int am = 0; am < 2; am++) {
            int p0 = pix0 + pm + am * 16 + qid;
            #pragma unroll
            for (int bn = 0; bn < 8; bn++) {
                int o = on + bn * 8 + 2 * qlan;
                float2 v0 = make_float2(acc[am][bn][0] * scale,
                                        acc[am][bn][1] * scale);
                float2 v1 = make_float2(acc[am][bn][2] * scale,
                                        acc[am][bn][3] * scale);
                *(float2*)&Yn[(size_t)p0 * CC + o]       = v0;
                *(float2*)&Yn[(size_t)(p0 + 8) * CC + o] = v1;
            }
        }
    } else {
        __half* Yn = (__half*)Y + (size_t)n * PLANE;
        #pragma unroll
        for (int am = 0; am < 2; am++) {
            int p0 = pix0 + pm + am * 16 + qid;
            #pragma unroll
            for (int bn = 0; bn < 8; bn++) {
                int o = on + bn * 8 + 2 * qlan;
                __half2 h0 = __floats2half2_rn(acc[am][bn][0] * scale,
                                               acc[am][bn][1] * scale);
                __half2 h1 = __floats2half2_rn(acc[am][bn][2] * scale,
                                               acc[am][bn][3] * scale);
                *(__half2*)&Yn[(size_t)p0 * CC + o]       = h0;
                *(__half2*)&Yn[(size_t)(p0 + 8) * CC + o] = h1;
            }
        }
    }
}

__global__ __launch_bounds__(256, 2)
void gemm_qkv(float* __restrict__ qp, float* __restrict__ kp,
              __half* __restrict__ vph, float qscale)
{
    const int z = blockIdx.z;
    const uint32_t* XH = g_xH + ((size_t)z * NB + blockIdx.y) * 64 * HW
                       - (size_t)blockIdx.y * 64 * HW;  // base per tensor; n added in core? no:
    // NOTE: core indexes planes with (kt*16+row)*HW + pix0 only; fold n here.
    const uint32_t* XHn = g_xH + (((size_t)z * NB + blockIdx.y) * 64) * HW;
    const uint32_t* XLn = g_xL + (((size_t)z * NB + blockIdx.y) * 64) * HW;
    (void)XH;
    if (z == 0)
        qkv_core<1>(g_wH, g_wL, XHn, XLn, qp, qscale);
    else if (z == 1)
        qkv_core<1>(g_wH + WSZ, g_wL + WSZ, XHn, XLn, kp, 1.f);
    else
        qkv_core<2>(g_wH + 2 * WSZ, g_wL + 2 * WSZ, XHn, XLn, vph, 1.f);
}

// ---------------------------------------------------------------------------
// out GEMM: X = pre-split bf16 planes (g_opH/g_opL). BM=64, 8 warps 2m x 4n.
// ---------------------------------------------------------------------------
__global__ __launch_bounds__(256, 2)
void gemm_out(float* __restrict__ Y)
{
    extern __shared__ uint32_t sm[];

    const int tid   = threadIdx.x;
    const int warp  = tid >> 5;
    const int lane  = tid & 31;
    const int qid   = lane >> 2;
    const int qlan  = lane & 3;
    const int pm    = (warp & 1) * 32;
    const int on    = (warp >> 1) * 32;
    const int n     = blockIdx.y;
    const int pix0  = blockIdx.x * 64;

    const uint32_t* WH = g_wH + 3 * WSZ;
    const uint32_t* WL = g_wL + 3 * WSZ;
    const uint32_t smb = (uint32_t)__cvta_generic_to_shared(sm);

    float acc[2][4][4];
    #pragma unroll
    for (int am = 0; am < 2; am++)
        #pragma unroll
        for (int bn = 0; bn < 4; bn++)
            #pragma unroll
            for (int j = 0; j < 4; j++) acc[am][bn][j] = 0.f;

    auto load_stage = [&](int kt, int s) {
        const uint32_t sb = smb + (uint32_t)(s * O_STAGE) * 4;
        #pragma unroll
        for (int it = 0; it < 2; it++) {
            int idx = tid + it * 256;
            int p = idx >> 3, c = idx & 7;
            int plane = c >> 2, cc = c & 3;
            const uint32_t* srcb = plane ? g_opL : g_opH;
            const uint32_t* src = srcb + ((size_t)(n * HW) + pix0 + p) * 64
                                  + kt * 16 + cc * 4;
            uint32_t dst = sb + (uint32_t)((plane ? O_XL_OFF : 0)
                                           + p * PW2 + cc * 4) * 4;
            cp_async16(dst, src);
        }
        #pragma unroll
        for (int it = 0; it < 4; it++) {
            int idx = tid + it * 256;
            int half = idx >> 9;
            int r = (idx >> 2) & 127;
            int c = idx & 3;
            const uint32_t* src = (half ? WL : WH) + r * 64 + kt * 16 + c * 4;
            uint32_t dst = sb + (uint32_t)((half ? O_WL_OFF : O_WH_OFF)
                                           + r * PW2 + c * 4) * 4;
            cp_async16(dst, src);
        }
    };

    load_stage(0, 0);
    asm volatile("cp.async.commit_group;\n");

    #pragma unroll
    for (int it = 0; it < 4; it++) {
        if (it < 3) {
            load_stage(it + 1, (it + 1) & 1);
            asm volatile("cp.async.commit_group;\n");
            asm volatile("cp.async.wait_group 1;\n");
        } else {
            asm volatile("cp.async.wait_group 0;\n");
        }
        __syncthreads();

        const int s = it & 1;
        const uint32_t* XsH = sm + s * O_STAGE;
        const uint32_t* XsL = sm + s * O_STAGE + O_XL_OFF;
        const uint32_t* WsH = sm + s * O_STAGE + O_WH_OFF;
        const uint32_t* WsL = sm + s * O_STAGE + O_WL_OFF;

        #pragma unroll
        for (int ks = 0; ks < 2; ks++) {
            const int kp2 = ks * 8 + qlan;

            uint32_t aH[2][4], aL[2][4];
            #pragma unroll
            for (int am = 0; am < 2; am++) {
                const int r = pm + am * 16 + qid;
                aH[am][0] = XsH[r * PW2 + kp2];
                aH[am][1] = XsH[(r + 8) * PW2 + kp2];
                aH[am][2] = XsH[r * PW2 + kp2 + 4];
                aH[am][3] = XsH[(r + 8) * PW2 + kp2 + 4];
                aL[am][0] = XsL[r * PW2 + kp2];
                aL[am][1] = XsL[(r + 8) * PW2 + kp2];
                aL[am][2] = XsL[r * PW2 + kp2 + 4];
                aL[am][3] = XsL[(r + 8) * PW2 + kp2 + 4];
            }
            #pragma unroll
            for (int bn = 0; bn < 4; bn++) {
                int bo = (on + bn * 8 + qid) * PW2 + kp2;
                uint32_t bH0 = WsH[bo], bH1 = WsH[bo + 4];
                uint32_t bL0 = WsL[bo], bL1 = WsL[bo + 4];
                #pragma unroll
                for (int am = 0; am < 2; am++) {
                    mma_bf16(acc[am][bn], aH[am], bH0, bH1);
                    mma_bf16(acc[am][bn], aH[am], bL0, bL1);
                    mma_bf16(acc[am][bn], aL[am], bH0, bH1);
                }
            }
        }
        if (it < 3) __syncthreads();
    }

    float* Yn = Y + (size_t)n * PLANE;
    #pragma unroll
    for (int am = 0; am < 2; am++) {
        int p0 = pix0 + pm + am * 16 + qid;
        #pragma unroll
        for (int bn = 0; bn < 4; bn++) {
            int o = on + bn * 8 + 2 * qlan;
            Yn[(size_t)o * HW + p0]           = acc[am][bn][0];
            Yn[(size_t)(o + 1) * HW + p0]     = acc[am][bn][1];
            Yn[(size_t)o * HW + p0 + 8]       = acc[am][bn][2];
            Yn[(size_t)(o + 1) * HW + p0 + 8] = acc[am][bn][3];
        }
    }
}

// ---------------------------------------------------------------------------
// Attention: one warp per pixel, 4 warps/block, linear pixels.
// K path fp32, V path fp16. Epilogue writes pre-split bf16 hi/lo planes.
// ---------------------------------------------------------------------------
__global__ __launch_bounds__(128)
void attn_kernel(const float* __restrict__ qp, const float* __restrict__ kp,
                 const __half* __restrict__ vph, const float* __restrict__ flow,
                 float* __restrict__ attn_out)
{
    const int warp = threadIdx.x >> 5;
    const int lane = threadIdx.x & 31;
    const int pix  = blockIdx.x * 4 + warp;
    const int n    = pix >> 12;
    const int yx   = pix & 4095;
    const int y    = yx >> 6;
    const int x    = yx & 63;
    const int head = lane >> 3;

    __shared__ float s_part[4][32][27];
    __shared__ float s_attn[4][NHEAD][K2];

    const float fx = flow[(size_t)(n * 2 + 0) * HW + yx];
    const float fy = flow[(size_t)(n * 2 + 1) * HW + yx];
    float vxn = 2.0f * ((float)x + fx) / 63.0f - 1.0f;
    float vyn = 2.0f * ((float)y + fy) / 63.0f - 1.0f;
    float xs = (vxn + 1.0f) * 0.5f * 63.0f;
    float ys = (vyn + 1.0f) * 0.5f * 63.0f;
    float bxf = floorf(xs), byf = floorf(ys);
    const float wx = xs - bxf;
    const float wy = ys - byf;
    const int ibx = (int)bxf - 2;
    const int iby = (int)byf - 2;

    unsigned mx = 0, my = 0;
    #pragma unroll
    for (int i = 0; i < 6; i++) {
        if ((unsigned)(ibx + i) <= 63u) mx |= 1u << i;
        if ((unsigned)(iby + i) <= 63u) my |= 1u << i;
    }

    const u64 wx2  = pk2(wx, wx),  nwx2 = pk2(-wx, -wx);
    const u64 wy2  = pk2(wy, wy),  nwy2 = pk2(-wy, -wy);

    const float4 q4 = *(const float4*)&qp[(size_t)pix * CC + lane * 4];
    const u64 q01 = pk2(q4.x, q4.y);
    const u64 q23 = pk2(q4.z, q4.w);

    const long long rowstride = (long long)WW * CC;
    const long long base0 = ((long long)(n << 12) + (long long)iby * WW + ibx) * CC
                          + lane * 4;

    // ================= K phase: logits (fp32) =================
    {
        u64 Ha[5][2], Hb[5][2];
        #pragma unroll
        for (int jc = 0; jc < 6; jc++) {
            const float* rowp = kp + base0 + jc * rowstride;
            const bool rowok = (my >> jc) & 1;
            float4 c[6];
            #pragma unroll
            for (int i = 0; i < 6; i++) {
                c[i] = make_float4(0.f, 0.f, 0.f, 0.f);
                if (rowok && ((mx >> i) & 1))
                    c[i] = *(const float4*)(rowp + i * CC);
            }
            u64 cp2[6][2];
            #pragma unroll
            for (int i = 0; i < 6; i++) {
                cp2[i][0] = pk2(c[i].x, c[i].y);
                cp2[i][1] = pk2(c[i].z, c[i].w);
            }
            u64 (*Hc)[2] = (jc & 1) ? Hb : Ha;
            u64 (*Hp)[2] = (jc & 1) ? Ha : Hb;
            #pragma unroll
            for (int i = 0; i < 5; i++) {
                Hc[i][0] = fma2(wx2, cp2[i+1][0], fma2(nwx2, cp2[i][0], cp2[i][0]));
                Hc[i][1] = fma2(wx2, cp2[i+1][1], fma2(nwx2, cp2[i][1], cp2[i][1]));
            }
            if (jc > 0) {
                #pragma unroll
                for (int i = 0; i < 5; i++) {
                    u64 t0 = fma2(wy2, Hc[i][0], fma2(nwy2, Hp[i][0], Hp[i][0]));
                    u64 t1 = fma2(wy2, Hc[i][1], fma2(nwy2, Hp[i][1], Hp[i][1]));
                    u64 d2 = fma2(q01, t0, fma2(q23, t1, 0ull));
                    float dx, dy; up2(d2, dx, dy);
                    s_part[warp][lane][(jc - 1) * 5 + i] = dx + dy;
                }
            }
        }
    }
    __syncwarp();

    const int kkl = (lane < K2) ? lane : 0;
    float hsum[4] = {0.f, 0.f, 0.f, 0.f};
    #pragma unroll
    for (int l = 0; l < 32; l++)
        hsum[l >> 3] += s_part[warp][l][kkl];

    float aout[4];
    #pragma unroll
    for (int h = 0; h < 4; h++) {
        float lg = (lane < K2) ? hsum[h] : -INFINITY;
        float m = lg;
        #pragma unroll
        for (int off = 16; off; off >>= 1)
            m = fmaxf(m, __shfl_xor_sync(0xffffffffu, m, off));
        float e = (lane < K2) ? __expf(lg - m) : 0.f;
        float s = e;
        #pragma unroll
        for (int off = 16; off; off >>= 1)
            s += __shfl_xor_sync(0xffffffffu, s, off);
        aout[h] = e / s;
    }
    if (lane < K2) {
        #pragma unroll
        for (int h = 0; h < 4; h++) {
            s_attn[warp][h][lane] = aout[h];
            attn_out[(size_t)((n * NHEAD + h) * K2 + lane) * HW + yx] = aout[h];
        }
    }
    __syncwarp();

    // ================= V phase (fp16 gather) =================
    u64 o01 = 0ull, o23 = 0ull;
    {
        u64 Ha[5][2], Hb[5][2];
        #pragma unroll
        for (int jc = 0; jc < 6; jc++) {
            const __half* rowp = vph + base0 + jc * rowstride;
            const bool rowok = (my >> jc) & 1;
            u64 cp2[6][2];
            #pragma unroll
            for (int i = 0; i < 6; i++) {
                uint2 raw = make_uint2(0u, 0u);
                if (rowok && ((mx >> i) & 1))
                    raw = *(const uint2*)(rowp + i * CC);
                float2 lo = __half22float2(*(const __half2*)&raw.x);
                float2 hi = __half22float2(*(const __half2*)&raw.y);
                cp2[i][0] = pk2(lo.x, lo.y);
                cp2[i][1] = pk2(hi.x, hi.y);
            }
            u64 (*Hc)[2] = (jc & 1) ? Hb : Ha;
            u64 (*Hp)[2] = (jc & 1) ? Ha : Hb;
            #pragma unroll
            for (int i = 0; i < 5; i++) {
                Hc[i][0] = fma2(wx2, cp2[i+1][0], fma2(nwx2, cp2[i][0], cp2[i][0]));
                Hc[i][1] = fma2(wx2, cp2[i+1][1], fma2(nwx2, cp2[i][1], cp2[i][1]));
            }
            if (jc > 0) {
                #pragma unroll
                for (int i = 0; i < 5; i++) {
                    float aw = s_attn[warp][head][(jc - 1) * 5 + i];
                    u64 aw2 = pk2(aw, aw);
                    u64 t0 = fma2(wy2, Hc[i][0], fma2(nwy2, Hp[i][0], Hp[i][0]));
                    u64 t1 = fma2(wy2, Hc[i][1], fma2(nwy2, Hp[i][1], Hp[i][1]));
                    o01 = fma2(aw2, t0, o01);
                    o23 = fma2(aw2, t1, o23);
                }
            }
        }
    }
    float4 out4;
    up2(o01, out4.x, out4.y);
    up2(o23, out4.z, out4.w);

    uint32_t h0, l0, h1, l1;
    sp2(out4.x, out4.y, h0, l0);
    sp2(out4.z, out4.w, h1, l1);
    *(uint2*)&g_opH[(size_t)pix * 64 + lane * 2] = make_uint2(h0, h1);
    *(uint2*)&g_opL[(size_t)pix * 64 + lane * 2] = make_uint2(l0, l1);
}

// ---------------------------------------------------------------------------
extern "C" void kernel_launch(void* const* d_in, const int* in_sizes, int n_in,
                              void* d_out, int out_size)
{
    const float* q    = (const float*)d_in[0];
    const float* k    = (const float*)d_in[1];
    const float* v    = (const float*)d_in[2];
    const float* flow = (const float*)d_in[3];
    const float* Wq   = (const float*)d_in[4];
    const float* Wk   = (const float*)d_in[5];
    const float* Wv   = (const float*)d_in[6];
    const float* Wfc  = (const float*)d_in[7];

    float* out  = (float*)d_out;
    float* attn = out + (size_t)NB * CC * HW;

    float *qp, *kp;
    __half* vph;
    cudaGetSymbolAddress((void**)&qp,  g_qp);
    cudaGetSymbolAddress((void**)&kp,  g_kp);
    cudaGetSymbolAddress((void**)&vph, g_vph);

    const size_t smem_qkv = 2 * Q_STAGE * sizeof(uint32_t);  // 75776
    const size_t smem_out = 2 * O_STAGE * sizeof(uint32_t);  // 61440
    cudaFuncSetAttribute(gemm_qkv, cudaFuncAttributeMaxDynamicSharedMemorySize,
                         (int)smem_qkv);
    cudaFuncSetAttribute(gemm_out, cudaFuncAttributeMaxDynamicSharedMemorySize,
                         (int)smem_out);

    const float qscale = 0.17677669529663687f;  // 1/sqrt(32)

    dim3 gps(4, 4);
    presplit_w<<<gps, 256>>>(Wq, Wk, Wv, Wfc);

    dim3 gpx(64, NB, 3);
    presplit_x<<<gpx, 256>>>(q, k, v);

    dim3 gqkv(HW / 128, NB, 3);
    gemm_qkv<<<gqkv, 256, smem_qkv>>>(qp, kp, vph, qscale);

    attn_kernel<<<NPIX / 4, 128>>>(qp, kp, vph, flow, attn);

    dim3 gg(HW / 64, NB);
    gemm_out<<<gg, 256, smem_out>>>(out);
}

// round 14
// speedup vs baseline: 1.0060x; 1.0060x over previous
#include <cuda_runtime.h>
#include <cuda_bf16.h>
#include <cuda_fp16.h>
#include <math.h>
#include <stdint.h>

// ---------------------------------------------------------------------------
// n=4, C=128, H=W=64, K_SIZE=5 (K2=25), N_HEAD=4, d=32
// Inputs: q, k, v, flow, Wq, Wk, Wv, Wfc
// Output: concat( out[4,128,64,64], attn[4,4,25,64,64] )
// ---------------------------------------------------------------------------

#define NB      4
#define CC      128
#define WW      64
#define HW      4096
#define NPIX    (NB*HW)
#define PLANE   (CC*HW)
#define K2      25
#define NHEAD   4

#define PW2     20                  // W packed-bf16 row stride (u32)

// qkv GEMM smem (u32), double buffered: X planes pre-split
#define QX       136                // X plane row stride (banks 8*qlan+qid)
#define Q_XL_OFF 2176               // 16*136
#define Q_WH_OFF 4352
#define Q_WL_OFF 6912               // 4352 + 128*20
#define Q_STAGE  9472               // 37888 B/stage

// out GEMM smem (u32), double buffered
#define O_XL_OFF 1280               // 64 x 20 per plane
#define O_WH_OFF 2560
#define O_WL_OFF 5120
#define O_STAGE  7680               // 30720 B/stage

#define WSZ     8192                // per-weight pre-split plane (128 o x 64 k2)

__device__ float    g_qp[NB*HW*CC];   // NHWC fp32, pre-scaled by 1/sqrt(d)
__device__ float    g_kp[NB*HW*CC];   // NHWC fp32
__device__ __half   g_vph[NB*HW*CC];  // NHWC fp16
__device__ uint32_t g_opH[NB*HW*64];  // attn output, packed bf16 hi pairs
__device__ uint32_t g_opL[NB*HW*64];  // attn output, packed bf16 lo pairs
__device__ uint32_t g_wH[4*WSZ];
__device__ uint32_t g_wL[4*WSZ];
__device__ uint32_t g_xH[3*NB*64*HW]; // q/k/v pre-split hi planes [t][n][k2][pix]
__device__ uint32_t g_xL[3*NB*64*HW]; // lo planes

// ---------------------------------------------------------------------------
// bf16x3 helpers
// ---------------------------------------------------------------------------
__device__ __forceinline__ uint16_t bfb(float f) {
    __nv_bfloat16 h = __float2bfloat16_rn(f);
    return *reinterpret_cast<uint16_t*>(&h);
}
__device__ __forceinline__ void sp2(float f0, float f1, uint32_t& ph, uint32_t& pl) {
    uint16_t h0 = bfb(f0), h1 = bfb(f1);
    float r0 = f0 - __uint_as_float((uint32_t)h0 << 16);   // exact
    float r1 = f1 - __uint_as_float((uint32_t)h1 << 16);
    uint16_t l0 = bfb(r0), l1 = bfb(r1);
    ph = ((uint32_t)h1 << 16) | h0;
    pl = ((uint32_t)l1 << 16) | l0;
}
__device__ __forceinline__ void mma_bf16(float* c, const uint32_t* a,
                                         uint32_t b0, uint32_t b1) {
    asm volatile(
        "mma.sync.aligned.m16n8k16.row.col.f32.bf16.bf16.f32 "
        "{%0,%1,%2,%3}, {%4,%5,%6,%7}, {%8,%9}, {%0,%1,%2,%3};\n"
        : "+f"(c[0]), "+f"(c[1]), "+f"(c[2]), "+f"(c[3])
        : "r"(a[0]), "r"(a[1]), "r"(a[2]), "r"(a[3]), "r"(b0), "r"(b1));
}
__device__ __forceinline__ void cp_async16(uint32_t dst_smem, const void* src) {
    asm volatile("cp.async.cg.shared.global [%0], [%1], 16;\n"
                 :: "r"(dst_smem), "l"(src));
}

// ---------------------------------------------------------------------------
// packed f32x2 helpers (attn kernel)
// ---------------------------------------------------------------------------
typedef unsigned long long u64;
__device__ __forceinline__ u64 pk2(float x, float y) {
    u64 r; asm("mov.b64 %0, {%1, %2};" : "=l"(r) : "f"(x), "f"(y)); return r;
}
__device__ __forceinline__ void up2(u64 v, float& x, float& y) {
    asm("mov.b64 {%0, %1}, %2;" : "=f"(x), "=f"(y) : "l"(v));
}
__device__ __forceinline__ u64 fma2(u64 a, u64 b, u64 c) {
    u64 d; asm("fma.rn.f32x2 %0, %1, %2, %3;" : "=l"(d) : "l"(a), "l"(b), "l"(c));
    return d;
}

// ---------------------------------------------------------------------------
// Pre-split all 4 weight matrices into packed bf16 hi/lo planes.
// ---------------------------------------------------------------------------
__global__ __launch_bounds__(256)
void presplit_w(const float* __restrict__ Wq, const float* __restrict__ Wk,
                const float* __restrict__ Wv, const float* __restrict__ Wfc)
{
    const int w = blockIdx.y;
    const float* W = (w == 0) ? Wq : (w == 1) ? Wk : (w == 2) ? Wv : Wfc;
    uint32_t* H = g_wH + w * WSZ;
    uint32_t* L = g_wL + w * WSZ;
    int base = blockIdx.x * 2048 + threadIdx.x;
    #pragma unroll
    for (int it = 0; it < 8; it++) {
        int idx = base + it * 256;
        float2 wv = *(const float2*)&W[idx * 2];
        uint32_t ph, pl; sp2(wv.x, wv.y, ph, pl);
        H[idx] = ph;
        L[idx] = pl;
    }
}

// ---------------------------------------------------------------------------
// Pre-split q/k/v (NCHW f32) into packed bf16 k-pair planes [t][n][k2][pix].
// block = (k2, n, t); reads two channel rows, packs (2k2, 2k2+1) per pixel.
// ---------------------------------------------------------------------------
__global__ __launch_bounds__(256)
void presplit_x(const float* __restrict__ q, const float* __restrict__ k,
                const float* __restrict__ v)
{
    const int k2 = blockIdx.x;      // 0..63
    const int n  = blockIdx.y;      // 0..3
    const int t  = blockIdx.z;      // 0..2
    const float* X = (t == 0) ? q : (t == 1) ? k : v;
    const float* r0 = X + ((size_t)n * CC + 2 * k2) * HW;
    const float* r1 = r0 + HW;
    uint32_t* H = g_xH + (((size_t)t * NB + n) * 64 + k2) * HW;
    uint32_t* L = g_xL + (((size_t)t * NB + n) * 64 + k2) * HW;
    #pragma unroll
    for (int it = 0; it < 16; it++) {
        int p = threadIdx.x + it * 256;
        uint32_t ph, pl;
        sp2(r0[p], r1[p], ph, pl);
        H[p] = ph;
        L[p] = pl;
    }
}

// ---------------------------------------------------------------------------
// qkv bf16x3 GEMM: X pre-split planes (no cvt in mainloop). BM=128.
// YMODE 1: f32 NHWC out.  YMODE 2: fp16 NHWC out.
// ---------------------------------------------------------------------------
template<int YMODE>
__device__ __forceinline__
void qkv_core(const uint32_t* __restrict__ WH, const uint32_t* __restrict__ WL,
              const uint32_t* __restrict__ XH, const uint32_t* __restrict__ XL,
              void* __restrict__ Y, float scale)
{
    extern __shared__ uint32_t sm[];

    const int tid   = threadIdx.x;
    const int warp  = tid >> 5;
    const int lane  = tid & 31;
    const int qid   = lane >> 2;
    const int qlan  = lane & 3;
    const int pm    = (warp & 3) * 32;
    const int on    = (warp >> 2) * 64;
    const int n     = blockIdx.y;
    const int pix0  = blockIdx.x * 128;

    const uint32_t smb = (uint32_t)__cvta_generic_to_shared(sm);

    float acc[2][8][4];
    #pragma unroll
    for (int am = 0; am < 2; am++)
        #pragma unroll
        for (int bn = 0; bn < 8; bn++)
            #pragma unroll
            for (int j = 0; j < 4; j++) acc[am][bn][j] = 0.f;

    auto load_stage = [&](int kt, int s) {
        const uint32_t sb = smb + (uint32_t)(s * Q_STAGE) * 4;
        // X planes: 2 x 16 rows x 128 u32 = 1024 chunks
        #pragma unroll
        for (int it = 0; it < 4; it++) {
            int idx = tid + it * 256;
            int plane = idx >> 9;
            int row = (idx >> 5) & 15;
            int c = idx & 31;
            const uint32_t* srcb = plane ? XL : XH;
            const uint32_t* src = srcb + (size_t)(kt * 16 + row) * HW + pix0 + c * 4;
            uint32_t dst = sb + (uint32_t)((plane ? Q_XL_OFF : 0)
                                           + row * QX + c * 4) * 4;
            cp_async16(dst, src);
        }
        // W planes: 2 x 128 rows x 4 chunks
        #pragma unroll
        for (int it = 0; it < 4; it++) {
            int idx = tid + it * 256;
            int half = idx >> 9;
            int r = (idx >> 2) & 127;
            int c = idx & 3;
            const uint32_t* src = (half ? WL : WH) + r * 64 + kt * 16 + c * 4;
            uint32_t dst = sb + (uint32_t)((half ? Q_WL_OFF : Q_WH_OFF)
                                           + r * PW2 + c * 4) * 4;
            cp_async16(dst, src);
        }
    };

    load_stage(0, 0);
    asm volatile("cp.async.commit_group;\n");

    #pragma unroll
    for (int it = 0; it < 4; it++) {
        if (it < 3) {
            load_stage(it + 1, (it + 1) & 1);
            asm volatile("cp.async.commit_group;\n");
            asm volatile("cp.async.wait_group 1;\n");
        } else {
            asm volatile("cp.async.wait_group 0;\n");
        }
        __syncthreads();

        const int s = it & 1;
        const uint32_t* XsH = sm + s * Q_STAGE;
        const uint32_t* XsL = sm + s * Q_STAGE + Q_XL_OFF;
        const uint32_t* WsH = sm + s * Q_STAGE + Q_WH_OFF;
        const uint32_t* WsL = sm + s * Q_STAGE + Q_WL_OFF;

        #pragma unroll
        for (int ks = 0; ks < 2; ks++) {
            const int k2c = ks * 8 + qlan;

            uint32_t aH[2][4], aL[2][4];
            #pragma unroll
            for (int am = 0; am < 2; am++) {
                const int r = pm + am * 16 + qid;
                aH[am][0] = XsH[k2c * QX + r];
                aH[am][1] = XsH[k2c * QX + r + 8];
                aH[am][2] = XsH[(k2c + 4) * QX + r];
                aH[am][3] = XsH[(k2c + 4) * QX + r + 8];
                aL[am][0] = XsL[k2c * QX + r];
                aL[am][1] = XsL[k2c * QX + r + 8];
                aL[am][2] = XsL[(k2c + 4) * QX + r];
                aL[am][3] = XsL[(k2c + 4) * QX + r + 8];
            }
            #pragma unroll
            for (int bn = 0; bn < 8; bn++) {
                int bo = (on + bn * 8 + qid) * PW2 + ks * 8 + qlan;
                uint32_t bH0 = WsH[bo], bH1 = WsH[bo + 4];
                uint32_t bL0 = WsL[bo], bL1 = WsL[bo + 4];
                #pragma unroll
                for (int am = 0; am < 2; am++) {
                    mma_bf16(acc[am][bn], aH[am], bH0, bH1);
                    mma_bf16(acc[am][bn], aH[am], bL0, bL1);
                    mma_bf16(acc[am][bn], aL[am], bH0, bH1);
                }
            }
        }
        if (it < 3) __syncthreads();
    }

    // ---- epilogue ----
    if (YMODE == 1) {
        float* Yn = (float*)Y + (size_t)n * PLANE;
        #pragma unroll
        for (int am = 0; am < 2; am++) {
            int p0 = pix0 + pm + am * 16 + qid;
            #pragma unroll
            for (int bn = 0; bn < 8; bn++) {
                int o = on + bn * 8 + 2 * qlan;
                float2 v0 = make_float2(acc[am][bn][0] * scale,
                                        acc[am][bn][1] * scale);
                float2 v1 = make_float2(acc[am][bn][2] * scale,
                                        acc[am][bn][3] * scale);
                *(float2*)&Yn[(size_t)p0 * CC + o]       = v0;
                *(float2*)&Yn[(size_t)(p0 + 8) * CC + o] = v1;
            }
        }
    } else {
        __half* Yn = (__half*)Y + (size_t)n * PLANE;
        #pragma unroll
        for (int am = 0; am < 2; am++) {
            int p0 = pix0 + pm + am * 16 + qid;
            #pragma unroll
            for (int bn = 0; bn < 8; bn++) {
                int o = on + bn * 8 + 2 * qlan;
                __half2 h0 = __floats2half2_rn(acc[am][bn][0] * scale,
                                               acc[am][bn][1] * scale);
                __half2 h1 = __floats2half2_rn(acc[am][bn][2] * scale,
                                               acc[am][bn][3] * scale);
                *(__half2*)&Yn[(size_t)p0 * CC + o]       = h0;
                *(__half2*)&Yn[(size_t)(p0 + 8) * CC + o] = h1;
            }
        }
    }
}

__global__ __launch_bounds__(256, 2)
void gemm_qkv(float* __restrict__ qp, float* __restrict__ kp,
              __half* __restrict__ vph, float qscale)
{
    const int z = blockIdx.z;
    const uint32_t* XH = g_xH + ((size_t)z * NB + blockIdx.y) * 64 * HW
                       - (size_t)blockIdx.y * 64 * HW;  // base per tensor; n added in core? no:
    // NOTE: core indexes planes with (kt*16+row)*HW + pix0 only; fold n here.
    const uint32_t* XHn = g_xH + (((size_t)z * NB + blockIdx.y) * 64) * HW;
    const uint32_t* XLn = g_xL + (((size_t)z * NB + blockIdx.y) * 64) * HW;
    (void)XH;
    if (z == 0)
        qkv_core<1>(g_wH, g_wL, XHn, XLn, qp, qscale);
    else if (z == 1)
        qkv_core<1>(g_wH + WSZ, g_wL + WSZ, XHn, XLn, kp, 1.f);
    else
        qkv_core<2>(g_wH + 2 * WSZ, g_wL + 2 * WSZ, XHn, XLn, vph, 1.f);
}

// ---------------------------------------------------------------------------
// out GEMM: X = pre-split bf16 planes (g_opH/g_opL). BM=64, 8 warps 2m x 4n.
// ---------------------------------------------------------------------------
__global__ __launch_bounds__(256, 2)
void gemm_out(float* __restrict__ Y)
{
    extern __shared__ uint32_t sm[];

    const int tid   = threadIdx.x;
    const int warp  = tid >> 5;
    const int lane  = tid & 31;
    const int qid   = lane >> 2;
    const int qlan  = lane & 3;
    const int pm    = (warp & 1) * 32;
    const int on    = (warp >> 1) * 32;
    const int n     = blockIdx.y;
    const int pix0  = blockIdx.x * 64;

    const uint32_t* WH = g_wH + 3 * WSZ;
    const uint32_t* WL = g_wL + 3 * WSZ;
    const uint32_t smb = (uint32_t)__cvta_generic_to_shared(sm);

    float acc[2][4][4];
    #pragma unroll
    for (int am = 0; am < 2; am++)
        #pragma unroll
        for (int bn = 0; bn < 4; bn++)
            #pragma unroll
            for (int j = 0; j < 4; j++) acc[am][bn][j] = 0.f;

    auto load_stage = [&](int kt, int s) {
        const uint32_t sb = smb + (uint32_t)(s * O_STAGE) * 4;
        #pragma unroll
        for (int it = 0; it < 2; it++) {
            int idx = tid + it * 256;
            int p = idx >> 3, c = idx & 7;
            int plane = c >> 2, cc = c & 3;
            const uint32_t* srcb = plane ? g_opL : g_opH;
            const uint32_t* src = srcb + ((size_t)(n * HW) + pix0 + p) * 64
                                  + kt * 16 + cc * 4;
            uint32_t dst = sb + (uint32_t)((plane ? O_XL_OFF : 0)
                                           + p * PW2 + cc * 4) * 4;
            cp_async16(dst, src);
        }
        #pragma unroll
        for (int it = 0; it < 4; it++) {
            int idx = tid + it * 256;
            int half = idx >> 9;
            int r = (idx >> 2) & 127;
            int c = idx & 3;
            const uint32_t* src = (half ? WL : WH) + r * 64 + kt * 16 + c * 4;
            uint32_t dst = sb + (uint32_t)((half ? O_WL_OFF : O_WH_OFF)
                                           + r * PW2 + c * 4) * 4;
            cp_async16(dst, src);
        }
    };

    load_stage(0, 0);
    asm volatile("cp.async.commit_group;\n");

    #pragma unroll
    for (int it = 0; it < 4; it++) {
        if (it < 3) {
            load_stage(it + 1, (it + 1) & 1);
            asm volatile("cp.async.commit_group;\n");
            asm volatile("cp.async.wait_group 1;\n");
        } else {
            asm volatile("cp.async.wait_group 0;\n");
        }
        __syncthreads();

        const int s = it & 1;
        const uint32_t* XsH = sm + s * O_STAGE;
        const uint32_t* XsL = sm + s * O_STAGE + O_XL_OFF;
        const uint32_t* WsH = sm + s * O_STAGE + O_WH_OFF;
        const uint32_t* WsL = sm + s * O_STAGE + O_WL_OFF;

        #pragma unroll
        for (int ks = 0; ks < 2; ks++) {
            const int kp2 = ks * 8 + qlan;

            uint32_t aH[2][4], aL[2][4];
            #pragma unroll
            for (int am = 0; am < 2; am++) {
                const int r = pm + am * 16 + qid;
                aH[am][0] = XsH[r * PW2 + kp2];
                aH[am][1] = XsH[(r + 8) * PW2 + kp2];
                aH[am][2] = XsH[r * PW2 + kp2 + 4];
                aH[am][3] = XsH[(r + 8) * PW2 + kp2 + 4];
                aL[am][0] = XsL[r * PW2 + kp2];
                aL[am][1] = XsL[(r + 8) * PW2 + kp2];
                aL[am][2] = XsL[r * PW2 + kp2 + 4];
                aL[am][3] = XsL[(r + 8) * PW2 + kp2 + 4];
            }
            #pragma unroll
            for (int bn = 0; bn < 4; bn++) {
                int bo = (on + bn * 8 + qid) * PW2 + kp2;
                uint32_t bH0 = WsH[bo], bH1 = WsH[bo + 4];
                uint32_t bL0 = WsL[bo], bL1 = WsL[bo + 4];
                #pragma unroll
                for (int am = 0; am < 2; am++) {
                    mma_bf16(acc[am][bn], aH[am], bH0, bH1);
                    mma_bf16(acc[am][bn], aH[am], bL0, bL1);
                    mma_bf16(acc[am][bn], aL[am], bH0, bH1);
                }
            }
        }
        if (it < 3) __syncthreads();
    }

    float* Yn = Y + (size_t)n * PLANE;
    #pragma unroll
    for (int am = 0; am < 2; am++) {
        int p0 = pix0 + pm + am * 16 + qid;
        #pragma unroll
        for (int bn = 0; bn < 4; bn++) {
            int o = on + bn * 8 + 2 * qlan;
            Yn[(size_t)o * HW + p0]           = acc[am][bn][0];
            Yn[(size_t)(o + 1) * HW + p0]     = acc[am][bn][1];
            Yn[(size_t)o * HW + p0 + 8]       = acc[am][bn][2];
            Yn[(size_t)(o + 1) * HW + p0 + 8] = acc[am][bn][3];
        }
    }
}

// ---------------------------------------------------------------------------
// Attention: one warp per pixel, 4 warps/block, linear pixels.
// K path fp32, V path fp16. Epilogue writes pre-split bf16 hi/lo planes.
// ---------------------------------------------------------------------------
__global__ __launch_bounds__(128)
void attn_kernel(const float* __restrict__ qp, const float* __restrict__ kp,
                 const __half* __restrict__ vph, const float* __restrict__ flow,
                 float* __restrict__ attn_out)
{
    const int warp = threadIdx.x >> 5;
    const int lane = threadIdx.x & 31;
    const int pix  = blockIdx.x * 4 + warp;
    const int n    = pix >> 12;
    const int yx   = pix & 4095;
    const int y    = yx >> 6;
    const int x    = yx & 63;
    const int head = lane >> 3;

    __shared__ float s_part[4][32][27];
    __shared__ float s_attn[4][NHEAD][K2];

    const float fx = flow[(size_t)(n * 2 + 0) * HW + yx];
    const float fy = flow[(size_t)(n * 2 + 1) * HW + yx];
    float vxn = 2.0f * ((float)x + fx) / 63.0f - 1.0f;
    float vyn = 2.0f * ((float)y + fy) / 63.0f - 1.0f;
    float xs = (vxn + 1.0f) * 0.5f * 63.0f;
    float ys = (vyn + 1.0f) * 0.5f * 63.0f;
    float bxf = floorf(xs), byf = floorf(ys);
    const float wx = xs - bxf;
    const float wy = ys - byf;
    const int ibx = (int)bxf - 2;
    const int iby = (int)byf - 2;

    unsigned mx = 0, my = 0;
    #pragma unroll
    for (int i = 0; i < 6; i++) {
        if ((unsigned)(ibx + i) <= 63u) mx |= 1u << i;
        if ((unsigned)(iby + i) <= 63u) my |= 1u << i;
    }

    const u64 wx2  = pk2(wx, wx),  nwx2 = pk2(-wx, -wx);
    const u64 wy2  = pk2(wy, wy),  nwy2 = pk2(-wy, -wy);

    const float4 q4 = *(const float4*)&qp[(size_t)pix * CC + lane * 4];
    const u64 q01 = pk2(q4.x, q4.y);
    const u64 q23 = pk2(q4.z, q4.w);

    const long long rowstride = (long long)WW * CC;
    const long long base0 = ((long long)(n << 12) + (long long)iby * WW + ibx) * CC
                          + lane * 4;

    // ================= K phase: logits (fp32) =================
    {
        u64 Ha[5][2], Hb[5][2];
        #pragma unroll
        for (int jc = 0; jc < 6; jc++) {
            const float* rowp = kp + base0 + jc * rowstride;
            const bool rowok = (my >> jc) & 1;
            float4 c[6];
            #pragma unroll
            for (int i = 0; i < 6; i++) {
                c[i] = make_float4(0.f, 0.f, 0.f, 0.f);
                if (rowok && ((mx >> i) & 1))
                    c[i] = *(const float4*)(rowp + i * CC);
            }
            u64 cp2[6][2];
            #pragma unroll
            for (int i = 0; i < 6; i++) {
                cp2[i][0] = pk2(c[i].x, c[i].y);
                cp2[i][1] = pk2(c[i].z, c[i].w);
            }
            u64 (*Hc)[2] = (jc & 1) ? Hb : Ha;
            u64 (*Hp)[2] = (jc & 1) ? Ha : Hb;
            #pragma unroll
            for (int i = 0; i < 5; i++) {
                Hc[i][0] = fma2(wx2, cp2[i+1][0], fma2(nwx2, cp2[i][0], cp2[i][0]));
                Hc[i][1] = fma2(wx2, cp2[i+1][1], fma2(nwx2, cp2[i][1], cp2[i][1]));
            }
            if (jc > 0) {
                #pragma unroll
                for (int i = 0; i < 5; i++) {
                    u64 t0 = fma2(wy2, Hc[i][0], fma2(nwy2, Hp[i][0], Hp[i][0]));
                    u64 t1 = fma2(wy2, Hc[i][1], fma2(nwy2, Hp[i][1], Hp[i][1]));
                    u64 d2 = fma2(q01, t0, fma2(q23, t1, 0ull));
                    float dx, dy; up2(d2, dx, dy);
                    s_part[warp][lane][(jc - 1) * 5 + i] = dx + dy;
                }
            }
        }
    }
    __syncwarp();

    const int kkl = (lane < K2) ? lane : 0;
    float hsum[4] = {0.f, 0.f, 0.f, 0.f};
    #pragma unroll
    for (int l = 0; l < 32; l++)
        hsum[l >> 3] += s_part[warp][l][kkl];

    float aout[4];
    #pragma unroll
    for (int h = 0; h < 4; h++) {
        float lg = (lane < K2) ? hsum[h] : -INFINITY;
        float m = lg;
        #pragma unroll
        for (int off = 16; off; off >>= 1)
            m = fmaxf(m, __shfl_xor_sync(0xffffffffu, m, off));
        float e = (lane < K2) ? __expf(lg - m) : 0.f;
        float s = e;
        #pragma unroll
        for (int off = 16; off; off >>= 1)
            s += __shfl_xor_sync(0xffffffffu, s, off);
        aout[h] = e / s;
    }
    if (lane < K2) {
        #pragma unroll
        for (int h = 0; h < 4; h++) {
            s_attn[warp][h][lane] = aout[h];
            attn_out[(size_t)((n * NHEAD + h) * K2 + lane) * HW + yx] = aout[h];
        }
    }
    __syncwarp();

    // ================= V phase (fp16 gather) =================
    u64 o01 = 0ull, o23 = 0ull;
    {
        u64 Ha[5][2], Hb[5][2];
        #pragma unroll
        for (int jc = 0; jc < 6; jc++) {
            const __half* rowp = vph + base0 + jc * rowstride;
            const bool rowok = (my >> jc) & 1;
            u64 cp2[6][2];
            #pragma unroll
            for (int i = 0; i < 6; i++) {
                uint2 raw = make_uint2(0u, 0u);
                if (rowok && ((mx >> i) & 1))
                    raw = *(const uint2*)(rowp + i * CC);
                float2 lo = __half22float2(*(const __half2*)&raw.x);
                float2 hi = __half22float2(*(const __half2*)&raw.y);
                cp2[i][0] = pk2(lo.x, lo.y);
                cp2[i][1] = pk2(hi.x, hi.y);
            }
            u64 (*Hc)[2] = (jc & 1) ? Hb : Ha;
            u64 (*Hp)[2] = (jc & 1) ? Ha : Hb;
            #pragma unroll
            for (int i = 0; i < 5; i++) {
                Hc[i][0] = fma2(wx2, cp2[i+1][0], fma2(nwx2, cp2[i][0], cp2[i][0]));
                Hc[i][1] = fma2(wx2, cp2[i+1][1], fma2(nwx2, cp2[i][1], cp2[i][1]));
            }
            if (jc > 0) {
                #pragma unroll
                for (int i = 0; i < 5; i++) {
                    float aw = s_attn[warp][head][(jc - 1) * 5 + i];
                    u64 aw2 = pk2(aw, aw);
                    u64 t0 = fma2(wy2, Hc[i][0], fma2(nwy2, Hp[i][0], Hp[i][0]));
                    u64 t1 = fma2(wy2, Hc[i][1], fma2(nwy2, Hp[i][1], Hp[i][1]));
                    o01 = fma2(aw2, t0, o01);
                    o23 = fma2(aw2, t1, o23);
                }
            }
        }
    }
    float4 out4;
    up2(o01, out4.x, out4.y);
    up2(o23, out4.z, out4.w);

    uint32_t h0, l0, h1, l1;
    sp2(out4.x, out4.y, h0, l0);
    sp2(out4.z, out4.w, h1, l1);
    *(uint2*)&g_opH[(size_t)pix * 64 + lane * 2] = make_uint2(h0, h1);
    *(uint2*)&g_opL[(size_t)pix * 64 + lane * 2] = make_uint2(l0, l1);
}

// ---------------------------------------------------------------------------
extern "C" void kernel_launch(void* const* d_in, const int* in_sizes, int n_in,
                              void* d_out, int out_size)
{
    const float* q    = (const float*)d_in[0];
    const float* k    = (const float*)d_in[1];
    const float* v    = (const float*)d_in[2];
    const float* flow = (const float*)d_in[3];
    const float* Wq   = (const float*)d_in[4];
    const float* Wk   = (const float*)d_in[5];
    const float* Wv   = (const float*)d_in[6];
    const float* Wfc  = (const float*)d_in[7];

    float* out  = (float*)d_out;
    float* attn = out + (size_t)NB * CC * HW;

    float *qp, *kp;
    __half* vph;
    cudaGetSymbolAddress((void**)&qp,  g_qp);
    cudaGetSymbolAddress((void**)&kp,  g_kp);
    cudaGetSymbolAddress((void**)&vph, g_vph);

    const size_t smem_qkv = 2 * Q_STAGE * sizeof(uint32_t);  // 75776
    const size_t smem_out = 2 * O_STAGE * sizeof(uint32_t);  // 61440
    cudaFuncSetAttribute(gemm_qkv, cudaFuncAttributeMaxDynamicSharedMemorySize,
                         (int)smem_qkv);
    cudaFuncSetAttribute(gemm_out, cudaFuncAttributeMaxDynamicSharedMemorySize,
                         (int)smem_out);

    const float qscale = 0.17677669529663687f;  // 1/sqrt(32)

    dim3 gps(4, 4);
    presplit_w<<<gps, 256>>>(Wq, Wk, Wv, Wfc);

    dim3 gpx(64, NB, 3);
    presplit_x<<<gpx, 256>>>(q, k, v);

    dim3 gqkv(HW / 128, NB, 3);
    gemm_qkv<<<gqkv, 256, smem_qkv>>>(qp, kp, vph, qscale);

    attn_kernel<<<NPIX / 4, 128>>>(qp, kp, vph, flow, attn);

    dim3 gg(HW / 64, NB);
    gemm_out<<<gg, 256, smem_out>>>(out);
}

// round 15
// speedup vs baseline: 1.0063x; 1.0003x over previous
#include <cuda_runtime.h>
#include <cuda_bf16.h>
#include <cuda_fp16.h>
#include <math.h>
#include <stdint.h>

// ---------------------------------------------------------------------------
// n=4, C=128, H=W=64, K_SIZE=5 (K2=25), N_HEAD=4, d=32
// Inputs: q, k, v, flow, Wq, Wk, Wv, Wfc
// Output: concat( out[4,128,64,64], attn[4,4,25,64,64] )
// ---------------------------------------------------------------------------

#define NB      4
#define CC      128
#define WW      64
#define HW      4096
#define NPIX    (NB*HW)
#define PLANE   (CC*HW)
#define K2      25
#define NHEAD   4

#define PW2     20                  // W packed-bf16 row stride (u32)

// qkv GEMM smem (u32), double buffered: X planes pre-split
#define QX       136                // X plane row stride (banks 8*qlan+qid)
#define Q_XL_OFF 2176               // 16*136
#define Q_WH_OFF 4352
#define Q_WL_OFF 6912               // 4352 + 128*20
#define Q_STAGE  9472               // 37888 B/stage

// out GEMM smem (u32), double buffered
#define O_XL_OFF 1280               // 64 x 20 per plane
#define O_WH_OFF 2560
#define O_WL_OFF 5120
#define O_STAGE  7680               // 30720 B/stage

#define WSZ     8192                // per-weight pre-split plane (128 o x 64 k2)

__device__ float    g_qp[NB*HW*CC];   // NHWC fp32, pre-scaled by 1/sqrt(d)
__device__ float    g_kp[NB*HW*CC];   // NHWC fp32
__device__ __half   g_vph[NB*HW*CC];  // NHWC fp16
__device__ uint32_t g_opH[NB*HW*64];  // attn output, packed bf16 hi pairs
__device__ uint32_t g_opL[NB*HW*64];  // attn output, packed bf16 lo pairs
__device__ uint32_t g_wH[4*WSZ];
__device__ uint32_t g_wL[4*WSZ];
__device__ uint32_t g_xH[3*NB*64*HW]; // q/k/v pre-split hi planes [t][n][k2][pix]
__device__ uint32_t g_xL[3*NB*64*HW]; // lo planes

// ---------------------------------------------------------------------------
// bf16x3 helpers
// ---------------------------------------------------------------------------
__device__ __forceinline__ uint16_t bfb(float f) {
    __nv_bfloat16 h = __float2bfloat16_rn(f);
    return *reinterpret_cast<uint16_t*>(&h);
}
__device__ __forceinline__ void sp2(float f0, float f1, uint32_t& ph, uint32_t& pl) {
    uint16_t h0 = bfb(f0), h1 = bfb(f1);
    float r0 = f0 - __uint_as_float((uint32_t)h0 << 16);   // exact
    float r1 = f1 - __uint_as_float((uint32_t)h1 << 16);
    uint16_t l0 = bfb(r0), l1 = bfb(r1);
    ph = ((uint32_t)h1 << 16) | h0;
    pl = ((uint32_t)l1 << 16) | l0;
}
__device__ __forceinline__ void mma_bf16(float* c, const uint32_t* a,
                                         uint32_t b0, uint32_t b1) {
    asm volatile(
        "mma.sync.aligned.m16n8k16.row.col.f32.bf16.bf16.f32 "
        "{%0,%1,%2,%3}, {%4,%5,%6,%7}, {%8,%9}, {%0,%1,%2,%3};\n"
        : "+f"(c[0]), "+f"(c[1]), "+f"(c[2]), "+f"(c[3])
        : "r"(a[0]), "r"(a[1]), "r"(a[2]), "r"(a[3]), "r"(b0), "r"(b1));
}
__device__ __forceinline__ void cp_async16(uint32_t dst_smem, const void* src) {
    asm volatile("cp.async.cg.shared.global [%0], [%1], 16;\n"
                 :: "r"(dst_smem), "l"(src));
}

// ---------------------------------------------------------------------------
// packed f32x2 helpers (attn kernel)
// ---------------------------------------------------------------------------
typedef unsigned long long u64;
__device__ __forceinline__ u64 pk2(float x, float y) {
    u64 r; asm("mov.b64 %0, {%1, %2};" : "=l"(r) : "f"(x), "f"(y)); return r;
}
__device__ __forceinline__ void up2(u64 v, float& x, float& y) {
    asm("mov.b64 {%0, %1}, %2;" : "=f"(x), "=f"(y) : "l"(v));
}
__device__ __forceinline__ u64 fma2(u64 a, u64 b, u64 c) {
    u64 d; asm("fma.rn.f32x2 %0, %1, %2, %3;" : "=l"(d) : "l"(a), "l"(b), "l"(c));
    return d;
}

// ---------------------------------------------------------------------------
// Pre-split all 4 weight matrices into packed bf16 hi/lo planes.
// ---------------------------------------------------------------------------
__global__ __launch_bounds__(256)
void presplit_w(const float* __restrict__ Wq, const float* __restrict__ Wk,
                const float* __restrict__ Wv, const float* __restrict__ Wfc)
{
    const int w = blockIdx.y;
    const float* W = (w == 0) ? Wq : (w == 1) ? Wk : (w == 2) ? Wv : Wfc;
    uint32_t* H = g_wH + w * WSZ;
    uint32_t* L = g_wL + w * WSZ;
    int base = blockIdx.x * 2048 + threadIdx.x;
    #pragma unroll
    for (int it = 0; it < 8; it++) {
        int idx = base + it * 256;
        float2 wv = *(const float2*)&W[idx * 2];
        uint32_t ph, pl; sp2(wv.x, wv.y, ph, pl);
        H[idx] = ph;
        L[idx] = pl;
    }
}

// ---------------------------------------------------------------------------
// Pre-split q/k/v (NCHW f32) into packed bf16 k-pair planes [t][n][k2][pix].
// block = (k2, n, t); reads two channel rows, packs (2k2, 2k2+1) per pixel.
// ---------------------------------------------------------------------------
__global__ __launch_bounds__(256)
void presplit_x(const float* __restrict__ q, const float* __restrict__ k,
                const float* __restrict__ v)
{
    const int k2 = blockIdx.x;      // 0..63
    const int n  = blockIdx.y;      // 0..3
    const int t  = blockIdx.z;      // 0..2
    const float* X = (t == 0) ? q : (t == 1) ? k : v;
    const float* r0 = X + ((size_t)n * CC + 2 * k2) * HW;
    const float* r1 = r0 + HW;
    uint32_t* H = g_xH + (((size_t)t * NB + n) * 64 + k2) * HW;
    uint32_t* L = g_xL + (((size_t)t * NB + n) * 64 + k2) * HW;
    #pragma unroll
    for (int it = 0; it < 16; it++) {
        int p = threadIdx.x + it * 256;
        uint32_t ph, pl;
        sp2(r0[p], r1[p], ph, pl);
        H[p] = ph;
        L[p] = pl;
    }
}

// ---------------------------------------------------------------------------
// qkv bf16x3 GEMM: X pre-split planes (no cvt in mainloop). BM=128.
// YMODE 1: f32 NHWC out.  YMODE 2: fp16 NHWC out.
// ---------------------------------------------------------------------------
template<int YMODE>
__device__ __forceinline__
void qkv_core(const uint32_t* __restrict__ WH, const uint32_t* __restrict__ WL,
              const uint32_t* __restrict__ XH, const uint32_t* __restrict__ XL,
              void* __restrict__ Y, float scale)
{
    extern __shared__ uint32_t sm[];

    const int tid   = threadIdx.x;
    const int warp  = tid >> 5;
    const int lane  = tid & 31;
    const int qid   = lane >> 2;
    const int qlan  = lane & 3;
    const int pm    = (warp & 3) * 32;
    const int on    = (warp >> 2) * 64;
    const int n     = blockIdx.y;
    const int pix0  = blockIdx.x * 128;

    const uint32_t smb = (uint32_t)__cvta_generic_to_shared(sm);

    float acc[2][8][4];
    #pragma unroll
    for (int am = 0; am < 2; am++)
        #pragma unroll
        for (int bn = 0; bn < 8; bn++)
            #pragma unroll
            for (int j = 0; j < 4; j++) acc[am][bn][j] = 0.f;

    auto load_stage = [&](int kt, int s) {
        const uint32_t sb = smb + (uint32_t)(s * Q_STAGE) * 4;
        // X planes: 2 x 16 rows x 128 u32 = 1024 chunks
        #pragma unroll
        for (int it = 0; it < 4; it++) {
            int idx = tid + it * 256;
            int plane = idx >> 9;
            int row = (idx >> 5) & 15;
            int c = idx & 31;
            const uint32_t* srcb = plane ? XL : XH;
            const uint32_t* src = srcb + (size_t)(kt * 16 + row) * HW + pix0 + c * 4;
            uint32_t dst = sb + (uint32_t)((plane ? Q_XL_OFF : 0)
                                           + row * QX + c * 4) * 4;
            cp_async16(dst, src);
        }
        // W planes: 2 x 128 rows x 4 chunks
        #pragma unroll
        for (int it = 0; it < 4; it++) {
            int idx = tid + it * 256;
            int half = idx >> 9;
            int r = (idx >> 2) & 127;
            int c = idx & 3;
            const uint32_t* src = (half ? WL : WH) + r * 64 + kt * 16 + c * 4;
            uint32_t dst = sb + (uint32_t)((half ? Q_WL_OFF : Q_WH_OFF)
                                           + r * PW2 + c * 4) * 4;
            cp_async16(dst, src);
        }
    };

    load_stage(0, 0);
    asm volatile("cp.async.commit_group;\n");

    #pragma unroll
    for (int it = 0; it < 4; it++) {
        if (it < 3) {
            load_stage(it + 1, (it + 1) & 1);
            asm volatile("cp.async.commit_group;\n");
            asm volatile("cp.async.wait_group 1;\n");
        } else {
            asm volatile("cp.async.wait_group 0;\n");
        }
        __syncthreads();

        const int s = it & 1;
        const uint32_t* XsH = sm + s * Q_STAGE;
        const uint32_t* XsL = sm + s * Q_STAGE + Q_XL_OFF;
        const uint32_t* WsH = sm + s * Q_STAGE + Q_WH_OFF;
        const uint32_t* WsL = sm + s * Q_STAGE + Q_WL_OFF;

        #pragma unroll
        for (int ks = 0; ks < 2; ks++) {
            const int k2c = ks * 8 + qlan;

            uint32_t aH[2][4], aL[2][4];
            #pragma unroll
            for (int am = 0; am < 2; am++) {
                const int r = pm + am * 16 + qid;
                aH[am][0] = XsH[k2c * QX + r];
                aH[am][1] = XsH[k2c * QX + r + 8];
                aH[am][2] = XsH[(k2c + 4) * QX + r];
                aH[am][3] = XsH[(k2c + 4) * QX + r + 8];
                aL[am][0] = XsL[k2c * QX + r];
                aL[am][1] = XsL[k2c * QX + r + 8];
                aL[am][2] = XsL[(k2c + 4) * QX + r];
                aL[am][3] = XsL[(k2c + 4) * QX + r + 8];
            }
            #pragma unroll
            for (int bn = 0; bn < 8; bn++) {
                int bo = (on + bn * 8 + qid) * PW2 + ks * 8 + qlan;
                uint32_t bH0 = WsH[bo], bH1 = WsH[bo + 4];
                uint32_t bL0 = WsL[bo], bL1 = WsL[bo + 4];
                #pragma unroll
                for (int am = 0; am < 2; am++) {
                    mma_bf16(acc[am][bn], aH[am], bH0, bH1);
                    mma_bf16(acc[am][bn], aH[am], bL0, bL1);
                    mma_bf16(acc[am][bn], aL[am], bH0, bH1);
                }
            }
        }
        if (it < 3) __syncthreads();
    }

    // ---- epilogue ----
    if (YMODE == 1) {
        float* Yn = (float*)Y + (size_t)n * PLANE;
        #pragma unroll
        for (int am = 0; am < 2; am++) {
            int p0 = pix0 + pm + am * 16 + qid;
            #pragma unroll
            for (int bn = 0; bn < 8; bn++) {
                int o = on + bn * 8 + 2 * qlan;
                float2 v0 = make_float2(acc[am][bn][0] * scale,
                                        acc[am][bn][1] * scale);
                float2 v1 = make_float2(acc[am][bn][2] * scale,
                                        acc[am][bn][3] * scale);
                *(float2*)&Yn[(size_t)p0 * CC + o]       = v0;
                *(float2*)&Yn[(size_t)(p0 + 8) * CC + o] = v1;
            }
        }
    } else {
        __half* Yn = (__half*)Y + (size_t)n * PLANE;
        #pragma unroll
        for (int am = 0; am < 2; am++) {
            int p0 = pix0 + pm + am * 16 + qid;
            #pragma unroll
            for (int bn = 0; bn < 8; bn++) {
                int o = on + bn * 8 + 2 * qlan;
                __half2 h0 = __floats2half2_rn(acc[am][bn][0] * scale,
                                               acc[am][bn][1] * scale);
                __half2 h1 = __floats2half2_rn(acc[am][bn][2] * scale,
                                               acc[am][bn][3] * scale);
                *(__half2*)&Yn[(size_t)p0 * CC + o]       = h0;
                *(__half2*)&Yn[(size_t)(p0 + 8) * CC + o] = h1;
            }
        }
    }
}

__global__ __launch_bounds__(256, 2)
void gemm_qkv(float* __restrict__ qp, float* __restrict__ kp,
              __half* __restrict__ vph, float qscale)
{
    const int z = blockIdx.z;
    const uint32_t* XH = g_xH + ((size_t)z * NB + blockIdx.y) * 64 * HW
                       - (size_t)blockIdx.y * 64 * HW;  // base per tensor; n added in core? no:
    // NOTE: core indexes planes with (kt*16+row)*HW + pix0 only; fold n here.
    const uint32_t* XHn = g_xH + (((size_t)z * NB + blockIdx.y) * 64) * HW;
    const uint32_t* XLn = g_xL + (((size_t)z * NB + blockIdx.y) * 64) * HW;
    (void)XH;
    if (z == 0)
        qkv_core<1>(g_wH, g_wL, XHn, XLn, qp, qscale);
    else if (z == 1)
        qkv_core<1>(g_wH + WSZ, g_wL + WSZ, XHn, XLn, kp, 1.f);
    else
        qkv_core<2>(g_wH + 2 * WSZ, g_wL + 2 * WSZ, XHn, XLn, vph, 1.f);
}

// ---------------------------------------------------------------------------
// out GEMM: X = pre-split bf16 planes (g_opH/g_opL). BM=64, 8 warps 2m x 4n.
// ---------------------------------------------------------------------------
__global__ __launch_bounds__(256, 2)
void gemm_out(float* __restrict__ Y)
{
    extern __shared__ uint32_t sm[];

    const int tid   = threadIdx.x;
    const int warp  = tid >> 5;
    const int lane  = tid & 31;
    const int qid   = lane >> 2;
    const int qlan  = lane & 3;
    const int pm    = (warp & 1) * 32;
    const int on    = (warp >> 1) * 32;
    const int n     = blockIdx.y;
    const int pix0  = blockIdx.x * 64;

    const uint32_t* WH = g_wH + 3 * WSZ;
    const uint32_t* WL = g_wL + 3 * WSZ;
    const uint32_t smb = (uint32_t)__cvta_generic_to_shared(sm);

    float acc[2][4][4];
    #pragma unroll
    for (int am = 0; am < 2; am++)
        #pragma unroll
        for (int bn = 0; bn < 4; bn++)
            #pragma unroll
            for (int j = 0; j < 4; j++) acc[am][bn][j] = 0.f;

    auto load_stage = [&](int kt, int s) {
        const uint32_t sb = smb + (uint32_t)(s * O_STAGE) * 4;
        #pragma unroll
        for (int it = 0; it < 2; it++) {
            int idx = tid + it * 256;
            int p = idx >> 3, c = idx & 7;
            int plane = c >> 2, cc = c & 3;
            const uint32_t* srcb = plane ? g_opL : g_opH;
            const uint32_t* src = srcb + ((size_t)(n * HW) + pix0 + p) * 64
                                  + kt * 16 + cc * 4;
            uint32_t dst = sb + (uint32_t)((plane ? O_XL_OFF : 0)
                                           + p * PW2 + cc * 4) * 4;
            cp_async16(dst, src);
        }
        #pragma unroll
        for (int it = 0; it < 4; it++) {
            int idx = tid + it * 256;
            int half = idx >> 9;
            int r = (idx >> 2) & 127;
            int c = idx & 3;
            const uint32_t* src = (half ? WL : WH) + r * 64 + kt * 16 + c * 4;
            uint32_t dst = sb + (uint32_t)((half ? O_WL_OFF : O_WH_OFF)
                                           + r * PW2 + c * 4) * 4;
            cp_async16(dst, src);
        }
    };

    load_stage(0, 0);
    asm volatile("cp.async.commit_group;\n");

    #pragma unroll
    for (int it = 0; it < 4; it++) {
        if (it < 3) {
            load_stage(it + 1, (it + 1) & 1);
            asm volatile("cp.async.commit_group;\n");
            asm volatile("cp.async.wait_group 1;\n");
        } else {
            asm volatile("cp.async.wait_group 0;\n");
        }
        __syncthreads();

        const int s = it & 1;
        const uint32_t* XsH = sm + s * O_STAGE;
        const uint32_t* XsL = sm + s * O_STAGE + O_XL_OFF;
        const uint32_t* WsH = sm + s * O_STAGE + O_WH_OFF;
        const uint32_t* WsL = sm + s * O_STAGE + O_WL_OFF;

        #pragma unroll
        for (int ks = 0; ks < 2; ks++) {
            const int kp2 = ks * 8 + qlan;

            uint32_t aH[2][4], aL[2][4];
            #pragma unroll
            for (int am = 0; am < 2; am++) {
                const int r = pm + am * 16 + qid;
                aH[am][0] = XsH[r * PW2 + kp2];
                aH[am][1] = XsH[(r + 8) * PW2 + kp2];
                aH[am][2] = XsH[r * PW2 + kp2 + 4];
                aH[am][3] = XsH[(r + 8) * PW2 + kp2 + 4];
                aL[am][0] = XsL[r * PW2 + kp2];
                aL[am][1] = XsL[(r + 8) * PW2 + kp2];
                aL[am][2] = XsL[r * PW2 + kp2 + 4];
                aL[am][3] = XsL[(r + 8) * PW2 + kp2 + 4];
            }
            #pragma unroll
            for (int bn = 0; bn < 4; bn++) {
                int bo = (on + bn * 8 + qid) * PW2 + kp2;
                uint32_t bH0 = WsH[bo], bH1 = WsH[bo + 4];
                uint32_t bL0 = WsL[bo], bL1 = WsL[bo + 4];
                #pragma unroll
                for (int am = 0; am < 2; am++) {
                    mma_bf16(acc[am][bn], aH[am], bH0, bH1);
                    mma_bf16(acc[am][bn], aH[am], bL0, bL1);
                    mma_bf16(acc[am][bn], aL[am], bH0, bH1);
                }
            }
        }
        if (it < 3) __syncthreads();
    }

    float* Yn = Y + (size_t)n * PLANE;
    #pragma unroll
    for (int am = 0; am < 2; am++) {
        int p0 = pix0 + pm + am * 16 + qid;
        #pragma unroll
        for (int bn = 0; bn < 4; bn++) {
            int o = on + bn * 8 + 2 * qlan;
            Yn[(size_t)o * HW + p0]           = acc[am][bn][0];
            Yn[(size_t)(o + 1) * HW + p0]     = acc[am][bn][1];
            Yn[(size_t)o * HW + p0 + 8]       = acc[am][bn][2];
            Yn[(size_t)(o + 1) * HW + p0 + 8] = acc[am][bn][3];
        }
    }
}

// ---------------------------------------------------------------------------
// Attention: one warp per pixel, 4 warps/block, linear pixels.
// K path fp32, V path fp16. Epilogue writes pre-split bf16 hi/lo planes.
// ---------------------------------------------------------------------------
__global__ __launch_bounds__(128)
void attn_kernel(const float* __restrict__ qp, const float* __restrict__ kp,
                 const __half* __restrict__ vph, const float* __restrict__ flow,
                 float* __restrict__ attn_out)
{
    const int warp = threadIdx.x >> 5;
    const int lane = threadIdx.x & 31;
    const int pix  = blockIdx.x * 4 + warp;
    const int n    = pix >> 12;
    const int yx   = pix & 4095;
    const int y    = yx >> 6;
    const int x    = yx & 63;
    const int head = lane >> 3;

    __shared__ float s_part[4][32][27];
    __shared__ float s_attn[4][NHEAD][K2];

    const float fx = flow[(size_t)(n * 2 + 0) * HW + yx];
    const float fy = flow[(size_t)(n * 2 + 1) * HW + yx];
    float vxn = 2.0f * ((float)x + fx) / 63.0f - 1.0f;
    float vyn = 2.0f * ((float)y + fy) / 63.0f - 1.0f;
    float xs = (vxn + 1.0f) * 0.5f * 63.0f;
    float ys = (vyn + 1.0f) * 0.5f * 63.0f;
    float bxf = floorf(xs), byf = floorf(ys);
    const float wx = xs - bxf;
    const float wy = ys - byf;
    const int ibx = (int)bxf - 2;
    const int iby = (int)byf - 2;

    unsigned mx = 0, my = 0;
    #pragma unroll
    for (int i = 0; i < 6; i++) {
        if ((unsigned)(ibx + i) <= 63u) mx |= 1u << i;
        if ((unsigned)(iby + i) <= 63u) my |= 1u << i;
    }

    const u64 wx2  = pk2(wx, wx),  nwx2 = pk2(-wx, -wx);
    const u64 wy2  = pk2(wy, wy),  nwy2 = pk2(-wy, -wy);

    const float4 q4 = *(const float4*)&qp[(size_t)pix * CC + lane * 4];
    const u64 q01 = pk2(q4.x, q4.y);
    const u64 q23 = pk2(q4.z, q4.w);

    const long long rowstride = (long long)WW * CC;
    const long long base0 = ((long long)(n << 12) + (long long)iby * WW + ibx) * CC
                          + lane * 4;

    // ================= K phase: logits (fp32) =================
    {
        u64 Ha[5][2], Hb[5][2];
        #pragma unroll
        for (int jc = 0; jc < 6; jc++) {
            const float* rowp = kp + base0 + jc * rowstride;
            const bool rowok = (my >> jc) & 1;
            float4 c[6];
            #pragma unroll
            for (int i = 0; i < 6; i++) {
                c[i] = make_float4(0.f, 0.f, 0.f, 0.f);
                if (rowok && ((mx >> i) & 1))
                    c[i] = *(const float4*)(rowp + i * CC);
            }
            u64 cp2[6][2];
            #pragma unroll
            for (int i = 0; i < 6; i++) {
                cp2[i][0] = pk2(c[i].x, c[i].y);
                cp2[i][1] = pk2(c[i].z, c[i].w);
            }
            u64 (*Hc)[2] = (jc & 1) ? Hb : Ha;
            u64 (*Hp)[2] = (jc & 1) ? Ha : Hb;
            #pragma unroll
            for (int i = 0; i < 5; i++) {
                Hc[i][0] = fma2(wx2, cp2[i+1][0], fma2(nwx2, cp2[i][0], cp2[i][0]));
                Hc[i][1] = fma2(wx2, cp2[i+1][1], fma2(nwx2, cp2[i][1], cp2[i][1]));
            }
            if (jc > 0) {
                #pragma unroll
                for (int i = 0; i < 5; i++) {
                    u64 t0 = fma2(wy2, Hc[i][0], fma2(nwy2, Hp[i][0], Hp[i][0]));
                    u64 t1 = fma2(wy2, Hc[i][1], fma2(nwy2, Hp[i][1], Hp[i][1]));
                    u64 d2 = fma2(q01, t0, fma2(q23, t1, 0ull));
                    float dx, dy; up2(d2, dx, dy);
                    s_part[warp][lane][(jc - 1) * 5 + i] = dx + dy;
                }
            }
        }
    }
    __syncwarp();

    const int kkl = (lane < K2) ? lane : 0;
    float hsum[4] = {0.f, 0.f, 0.f, 0.f};
    #pragma unroll
    for (int l = 0; l < 32; l++)
        hsum[l >> 3] += s_part[warp][l][kkl];

    float aout[4];
    #pragma unroll
    for (int h = 0; h < 4; h++) {
        float lg = (lane < K2) ? hsum[h] : -INFINITY;
        float m = lg;
        #pragma unroll
        for (int off = 16; off; off >>= 1)
            m = fmaxf(m, __shfl_xor_sync(0xffffffffu, m, off));
        float e = (lane < K2) ? __expf(lg - m) : 0.f;
        float s = e;
        #pragma unroll
        for (int off = 16; off; off >>= 1)
            s += __shfl_xor_sync(0xffffffffu, s, off);
        aout[h] = e / s;
    }
    if (lane < K2) {
        #pragma unroll
        for (int h = 0; h < 4; h++) {
            s_attn[warp][h][lane] = aout[h];
            attn_out[(size_t)((n * NHEAD + h) * K2 + lane) * HW + yx] = aout[h];
        }
    }
    __syncwarp();

    // ================= V phase (fp16 gather) =================
    u64 o01 = 0ull, o23 = 0ull;
    {
        u64 Ha[5][2], Hb[5][2];
        #pragma unroll
        for (int jc = 0; jc < 6; jc++) {
            const __half* rowp = vph + base0 + jc * rowstride;
            const bool rowok = (my >> jc) & 1;
            u64 cp2[6][2];
            #pragma unroll
            for (int i = 0; i < 6; i++) {
                uint2 raw = make_uint2(0u, 0u);
                if (rowok && ((mx >> i) & 1))
                    raw = *(const uint2*)(rowp + i * CC);
                float2 lo = __half22float2(*(const __half2*)&raw.x);
                float2 hi = __half22float2(*(const __half2*)&raw.y);
                cp2[i][0] = pk2(lo.x, lo.y);
                cp2[i][1] = pk2(hi.x, hi.y);
            }
            u64 (*Hc)[2] = (jc & 1) ? Hb : Ha;
            u64 (*Hp)[2] = (jc & 1) ? Ha : Hb;
            #pragma unroll
            for (int i = 0; i < 5; i++) {
                Hc[i][0] = fma2(wx2, cp2[i+1][0], fma2(nwx2, cp2[i][0], cp2[i][0]));
                Hc[i][1] = fma2(wx2, cp2[i+1][1], fma2(nwx2, cp2[i][1], cp2[i][1]));
            }
            if (jc > 0) {
                #pragma unroll
                for (int i = 0; i < 5; i++) {
                    float aw = s_attn[warp][head][(jc - 1) * 5 + i];
                    u64 aw2 = pk2(aw, aw);
                    u64 t0 = fma2(wy2, Hc[i][0], fma2(nwy2, Hp[i][0], Hp[i][0]));
                    u64 t1 = fma2(wy2, Hc[i][1], fma2(nwy2, Hp[i][1], Hp[i][1]));
                    o01 = fma2(aw2, t0, o01);
                    o23 = fma2(aw2, t1, o23);
                }
            }
        }
    }
    float4 out4;
    up2(o01, out4.x, out4.y);
    up2(o23, out4.z, out4.w);

    uint32_t h0, l0, h1, l1;
    sp2(out4.x, out4.y, h0, l0);
    sp2(out4.z, out4.w, h1, l1);
    *(uint2*)&g_opH[(size_t)pix * 64 + lane * 2] = make_uint2(h0, h1);
    *(uint2*)&g_opL[(size_t)pix * 64 + lane * 2] = make_uint2(l0, l1);
}

// ---------------------------------------------------------------------------
extern "C" void kernel_launch(void* const* d_in, const int* in_sizes, int n_in,
                              void* d_out, int out_size)
{
    const float* q    = (const float*)d_in[0];
    const float* k    = (const float*)d_in[1];
    const float* v    = (const float*)d_in[2];
    const float* flow = (const float*)d_in[3];
    const float* Wq   = (const float*)d_in[4];
    const float* Wk   = (const float*)d_in[5];
    const float* Wv   = (const float*)d_in[6];
    const float* Wfc  = (const float*)d_in[7];

    float* out  = (float*)d_out;
    float* attn = out + (size_t)NB * CC * HW;

    float *qp, *kp;
    __half* vph;
    cudaGetSymbolAddress((void**)&qp,  g_qp);
    cudaGetSymbolAddress((void**)&kp,  g_kp);
    cudaGetSymbolAddress((void**)&vph, g_vph);

    const size_t smem_qkv = 2 * Q_STAGE * sizeof(uint32_t);  // 75776
    const size_t smem_out = 2 * O_STAGE * sizeof(uint32_t);  // 61440
    cudaFuncSetAttribute(gemm_qkv, cudaFuncAttributeMaxDynamicSharedMemorySize,
                         (int)smem_qkv);
    cudaFuncSetAttribute(gemm_out, cudaFuncAttributeMaxDynamicSharedMemorySize,
                         (int)smem_out);

    const float qscale = 0.17677669529663687f;  // 1/sqrt(32)

    dim3 gps(4, 4);
    presplit_w<<<gps, 256>>>(Wq, Wk, Wv, Wfc);

    dim3 gpx(64, NB, 3);
    presplit_x<<<gpx, 256>>>(q, k, v);

    dim3 gqkv(HW / 128, NB, 3);
    gemm_qkv<<<gqkv, 256, smem_qkv>>>(qp, kp, vph, qscale);

    attn_kernel<<<NPIX / 4, 128>>>(qp, kp, vph, flow, attn);

    dim3 gg(HW / 64, NB);
    gemm_out<<<gg, 256, smem_out>>>(out);
}

// round 16
// speedup vs baseline: 1.1532x; 1.1460x over previous
#include <cuda_runtime.h>
#include <cuda_bf16.h>
#include <cuda_fp16.h>
#include <math.h>
#include <stdint.h>

// ---------------------------------------------------------------------------
// n=4, C=128, H=W=64, K_SIZE=5 (K2=25), N_HEAD=4, d=32
// Inputs: q, k, v, flow, Wq, Wk, Wv, Wfc
// Output: concat( out[4,128,64,64], attn[4,4,25,64,64] )
// ---------------------------------------------------------------------------

#define NB      4
#define CC      128
#define WW      64
#define HW      4096
#define NPIX    (NB*HW)
#define PLANE   (CC*HW)
#define K2      25
#define NHEAD   4

// qkv GEMM smem layout (u32 units), double buffered
#define PXK     132                 // X k-major row stride
#define PW2     20                  // W packed-bf16 row stride
#define WH_OFF  5120
#define WL_OFF  7680
#define STAGE_U32 10240
#define SMEM_U32 (2*STAGE_U32)      // 81920 B

// out GEMM smem layout (pre-split X planes), double buffered
#define O_XL_OFF 1280               // 64 rows x 20 u32 per plane
#define O_WH_OFF 2560
#define O_WL_OFF 5120
#define O_STAGE  7680               // 30720 B per stage

#define WSZ     8192                // per-weight pre-split plane (128 o x 64 k2)

__device__ float    g_qp[NB*HW*CC];   // NHWC fp32, pre-scaled by 1/sqrt(d)
__device__ float    g_kp[NB*HW*CC];   // NHWC fp32
__device__ __half   g_vph[NB*HW*CC];  // NHWC fp16 (V gather traffic halved)
__device__ uint32_t g_opH[NB*HW*64];  // attn output, packed bf16 hi pairs
__device__ uint32_t g_opL[NB*HW*64];  // attn output, packed bf16 lo pairs
__device__ uint32_t g_wH[4*WSZ];
__device__ uint32_t g_wL[4*WSZ];

// ---------------------------------------------------------------------------
// bf16x3 helpers
// ---------------------------------------------------------------------------
__device__ __forceinline__ uint16_t bfb(float f) {
    __nv_bfloat16 h = __float2bfloat16_rn(f);
    return *reinterpret_cast<uint16_t*>(&h);
}
__device__ __forceinline__ void sp2(float f0, float f1, uint32_t& ph, uint32_t& pl) {
    uint16_t h0 = bfb(f0), h1 = bfb(f1);
    float r0 = f0 - __uint_as_float((uint32_t)h0 << 16);   // exact
    float r1 = f1 - __uint_as_float((uint32_t)h1 << 16);
    uint16_t l0 = bfb(r0), l1 = bfb(r1);
    ph = ((uint32_t)h1 << 16) | h0;
    pl = ((uint32_t)l1 << 16) | l0;
}
__device__ __forceinline__ void mma_bf16(float* c, const uint32_t* a,
                                         uint32_t b0, uint32_t b1) {
    asm volatile(
        "mma.sync.aligned.m16n8k16.row.col.f32.bf16.bf16.f32 "
        "{%0,%1,%2,%3}, {%4,%5,%6,%7}, {%8,%9}, {%0,%1,%2,%3};\n"
        : "+f"(c[0]), "+f"(c[1]), "+f"(c[2]), "+f"(c[3])
        : "r"(a[0]), "r"(a[1]), "r"(a[2]), "r"(a[3]), "r"(b0), "r"(b1));
}
__device__ __forceinline__ void cp_async16(uint32_t dst_smem, const void* src) {
    asm volatile("cp.async.cg.shared.global [%0], [%1], 16;\n"
                 :: "r"(dst_smem), "l"(src));
}

// ---------------------------------------------------------------------------
// packed f32x2 helpers (attn kernel)
// ---------------------------------------------------------------------------
typedef unsigned long long u64;
__device__ __forceinline__ u64 pk2(float x, float y) {
    u64 r; asm("mov.b64 %0, {%1, %2};" : "=l"(r) : "f"(x), "f"(y)); return r;
}
__device__ __forceinline__ void up2(u64 v, float& x, float& y) {
    asm("mov.b64 {%0, %1}, %2;" : "=f"(x), "=f"(y) : "l"(v));
}
__device__ __forceinline__ u64 fma2(u64 a, u64 b, u64 c) {
    u64 d; asm("fma.rn.f32x2 %0, %1, %2, %3;" : "=l"(d) : "l"(a), "l"(b), "l"(c));
    return d;
}

// ---------------------------------------------------------------------------
// Pre-split all 4 weight matrices into packed bf16 hi/lo planes.
// ---------------------------------------------------------------------------
__global__ __launch_bounds__(256)
void presplit_w(const float* __restrict__ Wq, const float* __restrict__ Wk,
                const float* __restrict__ Wv, const float* __restrict__ Wfc)
{
    const int w = blockIdx.y;
    const float* W = (w == 0) ? Wq : (w == 1) ? Wk : (w == 2) ? Wv : Wfc;
    uint32_t* H = g_wH + w * WSZ;
    uint32_t* L = g_wL + w * WSZ;
    int base = blockIdx.x * 2048 + threadIdx.x;
    #pragma unroll
    for (int it = 0; it < 8; it++) {
        int idx = base + it * 256;
        float2 wv = *(const float2*)&W[idx * 2];
        uint32_t ph, pl; sp2(wv.x, wv.y, ph, pl);
        H[idx] = ph;
        L[idx] = pl;
    }
}

// ---------------------------------------------------------------------------
// qkv bf16x3 GEMM: X f32 NCHW (cp.async), register-side split. BM=128.
// YMODE 1: f32 NHWC out.  YMODE 2: fp16 NHWC out.
// ---------------------------------------------------------------------------
template<int YMODE>
__device__ __forceinline__
void qkv_core(const uint32_t* __restrict__ WH, const uint32_t* __restrict__ WL,
              const float* __restrict__ X, void* __restrict__ Y, float scale)
{
    extern __shared__ uint32_t sm[];

    const int tid   = threadIdx.x;
    const int warp  = tid >> 5;
    const int lane  = tid & 31;
    const int qid   = lane >> 2;
    const int qlan  = lane & 3;
    const int pm    = (warp & 3) * 32;
    const int on    = (warp >> 2) * 64;
    const int n     = blockIdx.y;
    const int pix0  = blockIdx.x * 128;

    const float* Xn = X + (size_t)n * PLANE;
    const uint32_t smb = (uint32_t)__cvta_generic_to_shared(sm);

    float acc[2][8][4];
    #pragma unroll
    for (int am = 0; am < 2; am++)
        #pragma unroll
        for (int bn = 0; bn < 8; bn++)
            #pragma unroll
            for (int j = 0; j < 4; j++) acc[am][bn][j] = 0.f;

    auto load_stage = [&](int kt, int s) {
        const uint32_t sb = smb + (uint32_t)(s * STAGE_U32) * 4;
        #pragma unroll
        for (int it = 0; it < 4; it++) {
            int idx = tid + it * 256;
            int kk = idx >> 5, c = idx & 31;
            const float* src = Xn + (size_t)(kt * 32 + kk) * HW + pix0 + c * 4;
            cp_async16(sb + (uint32_t)(kk * PXK + c * 4) * 4, src);
        }
        #pragma unroll
        for (int it = 0; it < 4; it++) {
            int idx = tid + it * 256;
            int half = idx >> 9;
            int r = (idx >> 2) & 127;
            int c = idx & 3;
            const uint32_t* src = (half ? WL : WH) + r * 64 + kt * 16 + c * 4;
            uint32_t dst = sb + (uint32_t)((half ? WL_OFF : WH_OFF)
                                           + r * PW2 + c * 4) * 4;
            cp_async16(dst, src);
        }
    };

    load_stage(0, 0);
    asm volatile("cp.async.commit_group;\n");

    #pragma unroll
    for (int it = 0; it < 4; it++) {
        if (it < 3) {
            load_stage(it + 1, (it + 1) & 1);
            asm volatile("cp.async.commit_group;\n");
            asm volatile("cp.async.wait_group 1;\n");
        } else {
            asm volatile("cp.async.wait_group 0;\n");
        }
        __syncthreads();

        const int s = it & 1;
        const float*    Xs  = (const float*)(sm + s * STAGE_U32);
        const uint32_t* WsH = sm + s * STAGE_U32 + WH_OFF;
        const uint32_t* WsL = sm + s * STAGE_U32 + WL_OFF;

        #pragma unroll
        for (int ks = 0; ks < 2; ks++) {
            const int kb = ks * 16 + 2 * qlan;

            uint32_t aH[2][4], aL[2][4];
            #pragma unroll
            for (int am = 0; am < 2; am++) {
                const int r = pm + am * 16 + qid;
                float f0 = Xs[kb * PXK + r];           float f1 = Xs[(kb + 1) * PXK + r];
                float f2 = Xs[kb * PXK + r + 8];       float f3 = Xs[(kb + 1) * PXK + r + 8];
                float f4 = Xs[(kb + 8) * PXK + r];     float f5 = Xs[(kb + 9) * PXK + r];
                float f6 = Xs[(kb + 8) * PXK + r + 8]; float f7 = Xs[(kb + 9) * PXK + r + 8];
                sp2(f0, f1, aH[am][0], aL[am][0]);
                sp2(f2, f3, aH[am][1], aL[am][1]);
                sp2(f4, f5, aH[am][2], aL[am][2]);
                sp2(f6, f7, aH[am][3], aL[am][3]);
            }
            #pragma unroll
            for (int bn = 0; bn < 8; bn++) {
                int bo = (on + bn * 8 + qid) * PW2 + ks * 8 + qlan;
                uint32_t bH0 = WsH[bo], bH1 = WsH[bo + 4];
                uint32_t bL0 = WsL[bo], bL1 = WsL[bo + 4];
                #pragma unroll
                for (int am = 0; am < 2; am++) {
                    mma_bf16(acc[am][bn], aH[am], bH0, bH1);
                    mma_bf16(acc[am][bn], aH[am], bL0, bL1);
                    mma_bf16(acc[am][bn], aL[am], bH0, bH1);
                }
            }
        }
        if (it < 3) __syncthreads();
    }

    // ---- epilogue ----
    if (YMODE == 1) {
        float* Yn = (float*)Y + (size_t)n * PLANE;
        #pragma unroll
        for (int am = 0; am < 2; am++) {
            int p0 = pix0 + pm + am * 16 + qid;
            #pragma unroll
            for (int bn = 0; bn < 8; bn++) {
                int o = on + bn * 8 + 2 * qlan;
                float2 v0 = make_float2(acc[am][bn][0] * scale,
                                        acc[am][bn][1] * scale);
                float2 v1 = make_float2(acc[am][bn][2] * scale,
                                        acc[am][bn][3] * scale);
                *(float2*)&Yn[(size_t)p0 * CC + o]       = v0;
                *(float2*)&Yn[(size_t)(p0 + 8) * CC + o] = v1;
            }
        }
    } else {
        __half* Yn = (__half*)Y + (size_t)n * PLANE;
        #pragma unroll
        for (int am = 0; am < 2; am++) {
            int p0 = pix0 + pm + am * 16 + qid;
            #pragma unroll
            for (int bn = 0; bn < 8; bn++) {
                int o = on + bn * 8 + 2 * qlan;
                __half2 h0 = __floats2half2_rn(acc[am][bn][0] * scale,
                                               acc[am][bn][1] * scale);
                __half2 h1 = __floats2half2_rn(acc[am][bn][2] * scale,
                                               acc[am][bn][3] * scale);
                *(__half2*)&Yn[(size_t)p0 * CC + o]       = h0;
                *(__half2*)&Yn[(size_t)(p0 + 8) * CC + o] = h1;
            }
        }
    }
}

__global__ __launch_bounds__(256, 2)
void gemm_qkv(const float* __restrict__ q, const float* __restrict__ k,
              const float* __restrict__ v,
              float* __restrict__ qp, float* __restrict__ kp,
              __half* __restrict__ vph, float qscale)
{
    const int z = blockIdx.z;
    if (z == 0)
        qkv_core<1>(g_wH, g_wL, q, qp, qscale);
    else if (z == 1)
        qkv_core<1>(g_wH + WSZ, g_wL + WSZ, k, kp, 1.f);
    else
        qkv_core<2>(g_wH + 2 * WSZ, g_wL + 2 * WSZ, v, vph, 1.f);
}

// ---------------------------------------------------------------------------
// out GEMM: X = pre-split bf16 planes (g_opH/g_opL) -> no cvt in mainloop.
// BM=64 pixels, BN=128 out, 8 warps 2m x 4n. Y f32 NCHW.
// ---------------------------------------------------------------------------
__global__ __launch_bounds__(256, 2)
void gemm_out(float* __restrict__ Y)
{
    extern __shared__ uint32_t sm[];

    const int tid   = threadIdx.x;
    const int warp  = tid >> 5;
    const int lane  = tid & 31;
    const int qid   = lane >> 2;
    const int qlan  = lane & 3;
    const int pm    = (warp & 1) * 32;
    const int on    = (warp >> 1) * 32;
    const int n     = blockIdx.y;
    const int pix0  = blockIdx.x * 64;

    const uint32_t* WH = g_wH + 3 * WSZ;
    const uint32_t* WL = g_wL + 3 * WSZ;
    const uint32_t smb = (uint32_t)__cvta_generic_to_shared(sm);

    float acc[2][4][4];
    #pragma unroll
    for (int am = 0; am < 2; am++)
        #pragma unroll
        for (int bn = 0; bn < 4; bn++)
            #pragma unroll
            for (int j = 0; j < 4; j++) acc[am][bn][j] = 0.f;

    auto load_stage = [&](int kt, int s) {
        const uint32_t sb = smb + (uint32_t)(s * O_STAGE) * 4;
        #pragma unroll
        for (int it = 0; it < 2; it++) {
            int idx = tid + it * 256;
            int p = idx >> 3, c = idx & 7;
            int plane = c >> 2, cc = c & 3;
            const uint32_t* srcb = plane ? g_opL : g_opH;
            const uint32_t* src = srcb + ((size_t)(n * HW) + pix0 + p) * 64
                                  + kt * 16 + cc * 4;
            uint32_t dst = sb + (uint32_t)((plane ? O_XL_OFF : 0)
                                           + p * PW2 + cc * 4) * 4;
            cp_async16(dst, src);
        }
        #pragma unroll
        for (int it = 0; it < 4; it++) {
            int idx = tid + it * 256;
            int half = idx >> 9;
            int r = (idx >> 2) & 127;
            int c = idx & 3;
            const uint32_t* src = (half ? WL : WH) + r * 64 + kt * 16 + c * 4;
            uint32_t dst = sb + (uint32_t)((half ? O_WL_OFF : O_WH_OFF)
                                           + r * PW2 + c * 4) * 4;
            cp_async16(dst, src);
        }
    };

    load_stage(0, 0);
    asm volatile("cp.async.commit_group;\n");

    #pragma unroll
    for (int it = 0; it < 4; it++) {
        if (it < 3) {
            load_stage(it + 1, (it + 1) & 1);
            asm volatile("cp.async.commit_group;\n");
            asm volatile("cp.async.wait_group 1;\n");
        } else {
            asm volatile("cp.async.wait_group 0;\n");
        }
        __syncthreads();

        const int s = it & 1;
        const uint32_t* XsH = sm + s * O_STAGE;
        const uint32_t* XsL = sm + s * O_STAGE + O_XL_OFF;
        const uint32_t* WsH = sm + s * O_STAGE + O_WH_OFF;
        const uint32_t* WsL = sm + s * O_STAGE + O_WL_OFF;

        #pragma unroll
        for (int ks = 0; ks < 2; ks++) {
            const int kp2 = ks * 8 + qlan;

            uint32_t aH[2][4], aL[2][4];
            #pragma unroll
            for (int am = 0; am < 2; am++) {
                const int r = pm + am * 16 + qid;
                aH[am][0] = XsH[r * PW2 + kp2];
                aH[am][1] = XsH[(r + 8) * PW2 + kp2];
                aH[am][2] = XsH[r * PW2 + kp2 + 4];
                aH[am][3] = XsH[(r + 8) * PW2 + kp2 + 4];
                aL[am][0] = XsL[r * PW2 + kp2];
                aL[am][1] = XsL[(r + 8) * PW2 + kp2];
                aL[am][2] = XsL[r * PW2 + kp2 + 4];
                aL[am][3] = XsL[(r + 8) * PW2 + kp2 + 4];
            }
            #pragma unroll
            for (int bn = 0; bn < 4; bn++) {
                int bo = (on + bn * 8 + qid) * PW2 + kp2;
                uint32_t bH0 = WsH[bo], bH1 = WsH[bo + 4];
                uint32_t bL0 = WsL[bo], bL1 = WsL[bo + 4];
                #pragma unroll
                for (int am = 0; am < 2; am++) {
                    mma_bf16(acc[am][bn], aH[am], bH0, bH1);
                    mma_bf16(acc[am][bn], aH[am], bL0, bL1);
                    mma_bf16(acc[am][bn], aL[am], bH0, bH1);
                }
            }
        }
        if (it < 3) __syncthreads();
    }

    float* Yn = Y + (size_t)n * PLANE;
    #pragma unroll
    for (int am = 0; am < 2; am++) {
        int p0 = pix0 + pm + am * 16 + qid;
        #pragma unroll
        for (int bn = 0; bn < 4; bn++) {
            int o = on + bn * 8 + 2 * qlan;
            Yn[(size_t)o * HW + p0]           = acc[am][bn][0];
            Yn[(size_t)(o + 1) * HW + p0]     = acc[am][bn][1];
            Yn[(size_t)o * HW + p0 + 8]       = acc[am][bn][2];
            Yn[(size_t)(o + 1) * HW + p0 + 8] = acc[am][bn][3];
        }
    }
}

// ---------------------------------------------------------------------------
// Attention: one warp per pixel, 4 warps/block, linear pixels.
// K path fp32, V path fp16; pre-split bf16 epilogue.
// Rolling-corner lerp (one corner live at a time) + launch_bounds(128,6):
// regs <= 85 -> 6 blocks/SM (24 warps) to hide the 72 gather LDGs.
// ---------------------------------------------------------------------------
__global__ __launch_bounds__(128, 6)
void attn_kernel(const float* __restrict__ qp, const float* __restrict__ kp,
                 const __half* __restrict__ vph, const float* __restrict__ flow,
                 float* __restrict__ attn_out)
{
    const int warp = threadIdx.x >> 5;
    const int lane = threadIdx.x & 31;
    const int pix  = blockIdx.x * 4 + warp;
    const int n    = pix >> 12;
    const int yx   = pix & 4095;
    const int y    = yx >> 6;
    const int x    = yx & 63;
    const int head = lane >> 3;

    __shared__ float s_part[4][32][27];
    __shared__ float s_attn[4][NHEAD][K2];

    const float fx = flow[(size_t)(n * 2 + 0) * HW + yx];
    const float fy = flow[(size_t)(n * 2 + 1) * HW + yx];
    float vxn = 2.0f * ((float)x + fx) / 63.0f - 1.0f;
    float vyn = 2.0f * ((float)y + fy) / 63.0f - 1.0f;
    float xs = (vxn + 1.0f) * 0.5f * 63.0f;
    float ys = (vyn + 1.0f) * 0.5f * 63.0f;
    float bxf = floorf(xs), byf = floorf(ys);
    const float wx = xs - bxf;
    const float wy = ys - byf;
    const int ibx = (int)bxf - 2;
    const int iby = (int)byf - 2;

    unsigned mx = 0, my = 0;
    #pragma unroll
    for (int i = 0; i < 6; i++) {
        if ((unsigned)(ibx + i) <= 63u) mx |= 1u << i;
        if ((unsigned)(iby + i) <= 63u) my |= 1u << i;
    }

    const u64 wx2  = pk2(wx, wx),  nwx2 = pk2(-wx, -wx);
    const u64 wy2  = pk2(wy, wy),  nwy2 = pk2(-wy, -wy);

    const float4 q4 = *(const float4*)&qp[(size_t)pix * CC + lane * 4];
    const u64 q01 = pk2(q4.x, q4.y);
    const u64 q23 = pk2(q4.z, q4.w);

    const long long rowstride = (long long)WW * CC;
    const long long base0 = ((long long)(n << 12) + (long long)iby * WW + ibx) * CC
                          + lane * 4;

    // ================= K phase: logits (fp32, rolling corner) =================
    {
        u64 Ha[5][2], Hb[5][2];
        #pragma unroll
        for (int jc = 0; jc < 6; jc++) {
            const float* rowp = kp + base0 + jc * rowstride;
            const bool rowok = (my >> jc) & 1;
            u64 (*Hc)[2] = (jc & 1) ? Hb : Ha;
            u64 (*Hp)[2] = (jc & 1) ? Ha : Hb;
            u64 p0 = 0ull, p1 = 0ull;
            #pragma unroll
            for (int i = 0; i < 6; i++) {
                float4 c = make_float4(0.f, 0.f, 0.f, 0.f);
                if (rowok && ((mx >> i) & 1))
                    c = *(const float4*)(rowp + i * CC);
                u64 c0 = pk2(c.x, c.y);
                u64 c1 = pk2(c.z, c.w);
                if (i > 0) {
                    Hc[i-1][0] = fma2(wx2, c0, fma2(nwx2, p0, p0));
                    Hc[i-1][1] = fma2(wx2, c1, fma2(nwx2, p1, p1));
                }
                p0 = c0; p1 = c1;
            }
            if (jc > 0) {
                #pragma unroll
                for (int i = 0; i < 5; i++) {
                    u64 t0 = fma2(wy2, Hc[i][0], fma2(nwy2, Hp[i][0], Hp[i][0]));
                    u64 t1 = fma2(wy2, Hc[i][1], fma2(nwy2, Hp[i][1], Hp[i][1]));
                    u64 d2 = fma2(q01, t0, fma2(q23, t1, 0ull));
                    float dx, dy; up2(d2, dx, dy);
                    s_part[warp][lane][(jc - 1) * 5 + i] = dx + dy;
                }
            }
        }
    }
    __syncwarp();

    const int kkl = (lane < K2) ? lane : 0;
    float hsum[4] = {0.f, 0.f, 0.f, 0.f};
    #pragma unroll
    for (int l = 0; l < 32; l++)
        hsum[l >> 3] += s_part[warp][l][kkl];

    float aout[4];
    #pragma unroll
    for (int h = 0; h < 4; h++) {
        float lg = (lane < K2) ? hsum[h] : -INFINITY;
        float m = lg;
        #pragma unroll
        for (int off = 16; off; off >>= 1)
            m = fmaxf(m, __shfl_xor_sync(0xffffffffu, m, off));
        float e = (lane < K2) ? __expf(lg - m) : 0.f;
        float s = e;
        #pragma unroll
        for (int off = 16; off; off >>= 1)
            s += __shfl_xor_sync(0xffffffffu, s, off);
        aout[h] = e / s;
    }
    if (lane < K2) {
        #pragma unroll
        for (int h = 0; h < 4; h++) {
            s_attn[warp][h][lane] = aout[h];
            attn_out[(size_t)((n * NHEAD + h) * K2 + lane) * HW + yx] = aout[h];
        }
    }
    __syncwarp();

    // ================= V phase (fp16, rolling corner) =================
    u64 o01 = 0ull, o23 = 0ull;
    {
        u64 Ha[5][2], Hb[5][2];
        #pragma unroll
        for (int jc = 0; jc < 6; jc++) {
            const __half* rowp = vph + base0 + jc * rowstride;
            const bool rowok = (my >> jc) & 1;
            u64 (*Hc)[2] = (jc & 1) ? Hb : Ha;
            u64 (*Hp)[2] = (jc & 1) ? Ha : Hb;
            u64 p0 = 0ull, p1 = 0ull;
            #pragma unroll
            for (int i = 0; i < 6; i++) {
                uint2 raw = make_uint2(0u, 0u);
                if (rowok && ((mx >> i) & 1))
                    raw = *(const uint2*)(rowp + i * CC);
                float2 lo = __half22float2(*(const __half2*)&raw.x);
                float2 hi = __half22float2(*(const __half2*)&raw.y);
                u64 c0 = pk2(lo.x, lo.y);
                u64 c1 = pk2(hi.x, hi.y);
                if (i > 0) {
                    Hc[i-1][0] = fma2(wx2, c0, fma2(nwx2, p0, p0));
                    Hc[i-1][1] = fma2(wx2, c1, fma2(nwx2, p1, p1));
                }
                p0 = c0; p1 = c1;
            }
            if (jc > 0) {
                #pragma unroll
                for (int i = 0; i < 5; i++) {
                    float aw = s_attn[warp][head][(jc - 1) * 5 + i];
                    u64 aw2 = pk2(aw, aw);
                    u64 t0 = fma2(wy2, Hc[i][0], fma2(nwy2, Hp[i][0], Hp[i][0]));
                    u64 t1 = fma2(wy2, Hc[i][1], fma2(nwy2, Hp[i][1], Hp[i][1]));
                    o01 = fma2(aw2, t0, o01);
                    o23 = fma2(aw2, t1, o23);
                }
            }
        }
    }
    float4 out4;
    up2(o01, out4.x, out4.y);
    up2(o23, out4.z, out4.w);

    // pre-split epilogue: packed bf16 hi/lo planes (same split gemm_out uses)
    uint32_t h0, l0, h1, l1;
    sp2(out4.x, out4.y, h0, l0);
    sp2(out4.z, out4.w, h1, l1);
    *(uint2*)&g_opH[(size_t)pix * 64 + lane * 2] = make_uint2(h0, h1);
    *(uint2*)&g_opL[(size_t)pix * 64 + lane * 2] = make_uint2(l0, l1);
}

// ---------------------------------------------------------------------------
extern "C" void kernel_launch(void* const* d_in, const int* in_sizes, int n_in,
                              void* d_out, int out_size)
{
    const float* q    = (const float*)d_in[0];
    const float* k    = (const float*)d_in[1];
    const float* v    = (const float*)d_in[2];
    const float* flow = (const float*)d_in[3];
    const float* Wq   = (const float*)d_in[4];
    const float* Wk   = (const float*)d_in[5];
    const float* Wv   = (const float*)d_in[6];
    const float* Wfc  = (const float*)d_in[7];

    float* out  = (float*)d_out;
    float* attn = out + (size_t)NB * CC * HW;

    float *qp, *kp;
    __half* vph;
    cudaGetSymbolAddress((void**)&qp,  g_qp);
    cudaGetSymbolAddress((void**)&kp,  g_kp);
    cudaGetSymbolAddress((void**)&vph, g_vph);

    const size_t smem_qkv = SMEM_U32 * sizeof(uint32_t);   // 81920
    const size_t smem_out = 2 * O_STAGE * sizeof(uint32_t); // 61440
    cudaFuncSetAttribute(gemm_qkv, cudaFuncAttributeMaxDynamicSharedMemorySize,
                         (int)smem_qkv);
    cudaFuncSetAttribute(gemm_out, cudaFuncAttributeMaxDynamicSharedMemorySize,
                         (int)smem_out);

    const float qscale = 0.17677669529663687f;  // 1/sqrt(32)

    dim3 gps(4, 4);
    presplit_w<<<gps, 256>>>(Wq, Wk, Wv, Wfc);

    dim3 gqkv(HW / 128, NB, 3);
    gemm_qkv<<<gqkv, 256, smem_qkv>>>(q, k, v, qp, kp, vph, qscale);

    attn_kernel<<<NPIX / 4, 128>>>(qp, kp, vph, flow, attn);

    dim3 gg(HW / 64, NB);
    gemm_out<<<gg, 256, smem_out>>>(out);
}